// round 1
// baseline (speedup 1.0000x reference)
#include <cuda_runtime.h>
#include <math.h>

// Problem constants
#define BQ   16384          // B*S rows
#define HIDC 2048
#define NH   16
#define DD   128
#define NBANK 4
#define EPSF 1e-6f

// Output layout in d_out (floats): out[BQ*HIDC], new_mem0[NH*DD*DD], new_norm0[NH*DD]
#define OUT_MEM  ((size_t)BQ * HIDC)
#define OUT_NORM (OUT_MEM + (size_t)NH * DD * DD)

// -------- scratch (static device globals; no runtime allocation) ----------
__device__ float g_q[(size_t)BQ * HIDC];     // q proj, then combined (in place)
__device__ float g_k[(size_t)BQ * HIDC];     // k proj
__device__ float g_v[(size_t)BQ * HIDC];     // v proj, then delta_v (in place)
__device__ float g_part[(size_t)NH * 64 * DD * DD];   // split-K partials for mem update
__device__ float g_nsum[(size_t)NH * 256 * DD];       // per-block sigma_k column sums
__device__ float g_weff[NH][NBANK];                   // softmax(bank_weights) * active

__device__ __forceinline__ float sigf(float x) {
    // elu(x)+1
    return x > 0.f ? x + 1.f : expf(x);
}

// ---------------------------------------------------------------------------
// K0: softmax of bank weights + bank-active flags
// ---------------------------------------------------------------------------
__global__ void prep_kernel(const float* __restrict__ bw, const float* __restrict__ mn) {
    __shared__ float bsum[NBANK];
    int tid = threadIdx.x;
    int w = tid >> 5, lane = tid & 31;
    if (w < NBANK) {
        float s = 0.f;
        for (int i = lane; i < NH * DD; i += 32) s += mn[w * NH * DD + i];
        #pragma unroll
        for (int o = 16; o; o >>= 1) s += __shfl_down_sync(0xffffffffu, s, o);
        if (lane == 0) bsum[w] = s;
    }
    __syncthreads();
    if (tid < NH) {
        float x0 = bw[tid * 4 + 0], x1 = bw[tid * 4 + 1];
        float x2 = bw[tid * 4 + 2], x3 = bw[tid * 4 + 3];
        float m = fmaxf(fmaxf(x0, x1), fmaxf(x2, x3));
        float e0 = expf(x0 - m), e1 = expf(x1 - m), e2 = expf(x2 - m), e3 = expf(x3 - m);
        float inv = 1.f / (e0 + e1 + e2 + e3);
        g_weff[tid][0] = e0 * inv * (bsum[0] >= EPSF ? 1.f : 0.f);
        g_weff[tid][1] = e1 * inv * (bsum[1] >= EPSF ? 1.f : 0.f);
        g_weff[tid][2] = e2 * inv * (bsum[2] >= EPSF ? 1.f : 0.f);
        g_weff[tid][3] = e3 * inv * (bsum[3] >= EPSF ? 1.f : 0.f);
    }
}

// ---------------------------------------------------------------------------
// K1/K4: SGEMM   C[m,n] = sum_k A[m,k] * B[n,k]   (torch Linear: x @ W.T)
// BM=BN=128, BK=16, 256 threads, 8x8 per-thread tile.
// ---------------------------------------------------------------------------
#define BM 128
#define BN 128
#define BKK 16

__global__ __launch_bounds__(256) void sgemm_nt(
    const float* __restrict__ A, const float* __restrict__ B,
    float* __restrict__ C, int M, int N, int K)
{
    __shared__ float As[BKK][BM + 4];
    __shared__ float Bs[BKK][BN + 4];
    int tid = threadIdx.x;
    int bm = blockIdx.y * BM;
    int bn = blockIdx.x * BN;
    int tx = tid & 15, ty = tid >> 4;   // tx: 8 cols, ty: 8 rows

    float acc[8][8];
    #pragma unroll
    for (int i = 0; i < 8; i++)
        #pragma unroll
        for (int j = 0; j < 8; j++) acc[i][j] = 0.f;

    for (int k0 = 0; k0 < K; k0 += BKK) {
        // load A tile (128 x 16) and B tile (128 x 16), each 512 float4s
        #pragma unroll
        for (int it = 0; it < 2; it++) {
            int id = tid + it * 256;        // 0..511
            int m = id >> 2, kq = id & 3;   // kq*4 = k offset within tile
            float4 av = *(const float4*)&A[(size_t)(bm + m) * K + k0 + kq * 4];
            As[kq * 4 + 0][m] = av.x; As[kq * 4 + 1][m] = av.y;
            As[kq * 4 + 2][m] = av.z; As[kq * 4 + 3][m] = av.w;
            float4 bv = *(const float4*)&B[(size_t)(bn + m) * K + k0 + kq * 4];
            Bs[kq * 4 + 0][m] = bv.x; Bs[kq * 4 + 1][m] = bv.y;
            Bs[kq * 4 + 2][m] = bv.z; Bs[kq * 4 + 3][m] = bv.w;
        }
        __syncthreads();
        #pragma unroll
        for (int kk = 0; kk < BKK; kk++) {
            float a[8], b[8];
            float4 a0 = *(float4*)&As[kk][ty * 8];
            float4 a1 = *(float4*)&As[kk][ty * 8 + 4];
            a[0]=a0.x; a[1]=a0.y; a[2]=a0.z; a[3]=a0.w;
            a[4]=a1.x; a[5]=a1.y; a[6]=a1.z; a[7]=a1.w;
            float4 b0 = *(float4*)&Bs[kk][tx * 8];
            float4 b1 = *(float4*)&Bs[kk][tx * 8 + 4];
            b[0]=b0.x; b[1]=b0.y; b[2]=b0.z; b[3]=b0.w;
            b[4]=b1.x; b[5]=b1.y; b[6]=b1.z; b[7]=b1.w;
            #pragma unroll
            for (int i = 0; i < 8; i++)
                #pragma unroll
                for (int j = 0; j < 8; j++)
                    acc[i][j] = fmaf(a[i], b[j], acc[i][j]);
        }
        __syncthreads();
    }
    #pragma unroll
    for (int i = 0; i < 8; i++) {
        float4 o0, o1;
        o0.x=acc[i][0]; o0.y=acc[i][1]; o0.z=acc[i][2]; o0.w=acc[i][3];
        o1.x=acc[i][4]; o1.y=acc[i][5]; o1.z=acc[i][6]; o1.w=acc[i][7];
        size_t off = (size_t)(bm + ty * 8 + i) * N + bn + tx * 8;
        *(float4*)&C[off]     = o0;
        *(float4*)&C[off + 4] = o1;
    }
}

// ---------------------------------------------------------------------------
// K2: bank retrieval + weighted combine. One block = (head h, 64 rows of b*s).
// combined is written in place over q (block reads exactly its own tile first).
// ---------------------------------------------------------------------------
__global__ __launch_bounds__(256) void combined_kernel(
    const float* __restrict__ q, const float* __restrict__ memories,
    const float* __restrict__ mnorms, float* __restrict__ comb)
{
    __shared__ float sq[64][DD + 1];     // sigma(q) tile
    __shared__ float ms[16][DD + 4];     // memory d-chunk
    __shared__ float mn[NBANK][DD];
    __shared__ float csm[64][NBANK];     // per-row per-bank coefficient
    int h = blockIdx.y;
    int row0 = blockIdx.x * 64;
    int tid = threadIdx.x;

    // load sigma(q) tile: 64 x 128 floats = 2048 float4s
    #pragma unroll
    for (int it = 0; it < 8; it++) {
        int id = tid + it * 256;
        int r = id >> 5, c4 = id & 31;
        float4 v = *(const float4*)&q[(size_t)(row0 + r) * HIDC + h * DD + c4 * 4];
        sq[r][c4 * 4 + 0] = sigf(v.x); sq[r][c4 * 4 + 1] = sigf(v.y);
        sq[r][c4 * 4 + 2] = sigf(v.z); sq[r][c4 * 4 + 3] = sigf(v.w);
    }
    #pragma unroll
    for (int it = 0; it < 2; it++) {
        int id = tid + it * 256;            // 0..511
        int n = id >> 7, d = id & 127;
        mn[n][d] = mnorms[(size_t)(n * NH + h) * DD + d];
    }
    __syncthreads();

    // per-row per-bank norm and coefficient: 64 rows * 4 banks = 256 threads
    {
        int row = tid >> 2, n = tid & 3;
        float s = 0.f;
        #pragma unroll 8
        for (int d = 0; d < DD; d++) s += sq[row][d] * mn[n][d];
        csm[row][n] = g_weff[h][n] / fmaxf(s, EPSF);
    }
    __syncthreads();

    int tx = tid & 15, ty = tid >> 4;       // tx: 8 cols of e, ty: 4 rows
    float fin[4][8];
    #pragma unroll
    for (int i = 0; i < 4; i++)
        #pragma unroll
        for (int j = 0; j < 8; j++) fin[i][j] = 0.f;

    for (int n = 0; n < NBANK; n++) {
        float acc[4][8];
        #pragma unroll
        for (int i = 0; i < 4; i++)
            #pragma unroll
            for (int j = 0; j < 8; j++) acc[i][j] = 0.f;
        const float* mbase = memories + (size_t)(n * NH + h) * DD * DD;
        for (int dc = 0; dc < 8; dc++) {
            #pragma unroll
            for (int it = 0; it < 2; it++) {
                int id = tid + it * 256;    // 0..511 float4s
                int kr = id >> 5, c4 = id & 31;
                float4 v = *(const float4*)&mbase[(size_t)(dc * 16 + kr) * DD + c4 * 4];
                *(float4*)&ms[kr][c4 * 4] = v;
            }
            __syncthreads();
            #pragma unroll
            for (int kk = 0; kk < 16; kk++) {
                int d = dc * 16 + kk;
                float a0 = sq[ty * 4 + 0][d], a1 = sq[ty * 4 + 1][d];
                float a2 = sq[ty * 4 + 2][d], a3 = sq[ty * 4 + 3][d];
                float4 b0 = *(float4*)&ms[kk][tx * 8];
                float4 b1 = *(float4*)&ms[kk][tx * 8 + 4];
                float b[8] = {b0.x,b0.y,b0.z,b0.w,b1.x,b1.y,b1.z,b1.w};
                #pragma unroll
                for (int j = 0; j < 8; j++) {
                    acc[0][j] = fmaf(a0, b[j], acc[0][j]);
                    acc[1][j] = fmaf(a1, b[j], acc[1][j]);
                    acc[2][j] = fmaf(a2, b[j], acc[2][j]);
                    acc[3][j] = fmaf(a3, b[j], acc[3][j]);
                }
            }
            __syncthreads();
        }
        #pragma unroll
        for (int i = 0; i < 4; i++) {
            float c = csm[ty * 4 + i][n];
            #pragma unroll
            for (int j = 0; j < 8; j++) fin[i][j] = fmaf(c, acc[i][j], fin[i][j]);
        }
    }
    #pragma unroll
    for (int i = 0; i < 4; i++) {
        float4 o0, o1;
        o0.x=fin[i][0]; o0.y=fin[i][1]; o0.z=fin[i][2]; o0.w=fin[i][3];
        o1.x=fin[i][4]; o1.y=fin[i][5]; o1.z=fin[i][6]; o1.w=fin[i][7];
        size_t off = (size_t)(row0 + ty * 4 + i) * HIDC + h * DD + tx * 8;
        *(float4*)&comb[off]     = o0;
        *(float4*)&comb[off + 4] = o1;
    }
}

// ---------------------------------------------------------------------------
// K3a: delta_v = v - (sigma_k @ mem0)/knorm, in place over v.
// Also writes per-block sigma_k column sums (for new_norm0).
// ---------------------------------------------------------------------------
__global__ __launch_bounds__(256) void deltav_kernel(
    const float* __restrict__ k, float* __restrict__ v,
    const float* __restrict__ memories, const float* __restrict__ mnorms,
    float* __restrict__ nsum)
{
    __shared__ float sk[64][DD + 1];
    __shared__ float ms[16][DD + 4];
    __shared__ float mn0[DD];
    __shared__ float kn[64];
    __shared__ float csum[2][DD];
    int h = blockIdx.y;
    int row0 = blockIdx.x * 64;
    int tid = threadIdx.x;

    #pragma unroll
    for (int it = 0; it < 8; it++) {
        int id = tid + it * 256;
        int r = id >> 5, c4 = id & 31;
        float4 vv = *(const float4*)&k[(size_t)(row0 + r) * HIDC + h * DD + c4 * 4];
        sk[r][c4 * 4 + 0] = sigf(vv.x); sk[r][c4 * 4 + 1] = sigf(vv.y);
        sk[r][c4 * 4 + 2] = sigf(vv.z); sk[r][c4 * 4 + 3] = sigf(vv.w);
    }
    if (tid < DD) mn0[tid] = mnorms[(size_t)h * DD + tid];   // bank 0
    __syncthreads();

    if (tid < 64) {
        float s = 0.f;
        #pragma unroll 8
        for (int d = 0; d < DD; d++) s += sk[tid][d] * mn0[d];
        kn[tid] = fmaxf(s, EPSF);
    }
    // sigma_k column sums over this 64-row tile
    {
        int col = tid & 127, half = tid >> 7;
        float s = 0.f;
        #pragma unroll 8
        for (int r = half * 32; r < half * 32 + 32; r++) s += sk[r][col];
        csum[half][col] = s;
    }
    __syncthreads();
    if (tid < DD)
        nsum[(size_t)(h * 256 + blockIdx.x) * DD + tid] = csum[0][tid] + csum[1][tid];

    int tx = tid & 15, ty = tid >> 4;
    float acc[4][8];
    #pragma unroll
    for (int i = 0; i < 4; i++)
        #pragma unroll
        for (int j = 0; j < 8; j++) acc[i][j] = 0.f;

    const float* mbase = memories + (size_t)h * DD * DD;    // bank 0
    for (int dc = 0; dc < 8; dc++) {
        #pragma unroll
        for (int it = 0; it < 2; it++) {
            int id = tid + it * 256;
            int kr = id >> 5, c4 = id & 31;
            float4 vv = *(const float4*)&mbase[(size_t)(dc * 16 + kr) * DD + c4 * 4];
            *(float4*)&ms[kr][c4 * 4] = vv;
        }
        __syncthreads();
        #pragma unroll
        for (int kk = 0; kk < 16; kk++) {
            int d = dc * 16 + kk;
            float a0 = sk[ty * 4 + 0][d], a1 = sk[ty * 4 + 1][d];
            float a2 = sk[ty * 4 + 2][d], a3 = sk[ty * 4 + 3][d];
            float4 b0 = *(float4*)&ms[kk][tx * 8];
            float4 b1 = *(float4*)&ms[kk][tx * 8 + 4];
            float b[8] = {b0.x,b0.y,b0.z,b0.w,b1.x,b1.y,b1.z,b1.w};
            #pragma unroll
            for (int j = 0; j < 8; j++) {
                acc[0][j] = fmaf(a0, b[j], acc[0][j]);
                acc[1][j] = fmaf(a1, b[j], acc[1][j]);
                acc[2][j] = fmaf(a2, b[j], acc[2][j]);
                acc[3][j] = fmaf(a3, b[j], acc[3][j]);
            }
        }
        __syncthreads();
    }
    #pragma unroll
    for (int i = 0; i < 4; i++) {
        float inv = 1.f / kn[ty * 4 + i];
        size_t off = (size_t)(row0 + ty * 4 + i) * HIDC + h * DD + tx * 8;
        float4 v0 = *(float4*)&v[off];
        float4 v1 = *(float4*)&v[off + 4];
        v0.x -= acc[i][0]*inv; v0.y -= acc[i][1]*inv; v0.z -= acc[i][2]*inv; v0.w -= acc[i][3]*inv;
        v1.x -= acc[i][4]*inv; v1.y -= acc[i][5]*inv; v1.z -= acc[i][6]*inv; v1.w -= acc[i][7]*inv;
        *(float4*)&v[off]     = v0;
        *(float4*)&v[off + 4] = v1;
    }
}

// ---------------------------------------------------------------------------
// K3b: mem_update split-K: P[d,e] = sum_{r in slice} sigma_k[r,d]*delta_v[r,e]
// grid (64 slices of 256 rows, NH heads). Deterministic (no atomics).
// ---------------------------------------------------------------------------
__global__ __launch_bounds__(256) void memu_kernel(
    const float* __restrict__ k, const float* __restrict__ dv,
    float* __restrict__ part)
{
    __shared__ float sk[16][DD + 4];
    __shared__ float sv[16][DD + 4];
    int h = blockIdx.y;
    int r0 = blockIdx.x * 256;
    int tid = threadIdx.x;
    int tx = tid & 15, ty = tid >> 4;   // tx: e cols (8), ty: d rows (8)

    float acc[8][8];
    #pragma unroll
    for (int i = 0; i < 8; i++)
        #pragma unroll
        for (int j = 0; j < 8; j++) acc[i][j] = 0.f;

    for (int rc = 0; rc < 16; rc++) {
        #pragma unroll
        for (int it = 0; it < 2; it++) {
            int id = tid + it * 256;
            int rr = id >> 5, c4 = id & 31;
            size_t off = (size_t)(r0 + rc * 16 + rr) * HIDC + h * DD + c4 * 4;
            float4 kv = *(const float4*)&k[off];
            sk[rr][c4*4+0] = sigf(kv.x); sk[rr][c4*4+1] = sigf(kv.y);
            sk[rr][c4*4+2] = sigf(kv.z); sk[rr][c4*4+3] = sigf(kv.w);
            float4 vv = *(const float4*)&dv[off];
            *(float4*)&sv[rr][c4 * 4] = vv;
        }
        __syncthreads();
        #pragma unroll
        for (int rr = 0; rr < 16; rr++) {
            float4 a0 = *(float4*)&sk[rr][ty * 8];
            float4 a1 = *(float4*)&sk[rr][ty * 8 + 4];
            float a[8] = {a0.x,a0.y,a0.z,a0.w,a1.x,a1.y,a1.z,a1.w};
            float4 b0 = *(float4*)&sv[rr][tx * 8];
            float4 b1 = *(float4*)&sv[rr][tx * 8 + 4];
            float b[8] = {b0.x,b0.y,b0.z,b0.w,b1.x,b1.y,b1.z,b1.w};
            #pragma unroll
            for (int i = 0; i < 8; i++)
                #pragma unroll
                for (int j = 0; j < 8; j++)
                    acc[i][j] = fmaf(a[i], b[j], acc[i][j]);
        }
        __syncthreads();
    }
    size_t base = ((size_t)(h * 64 + blockIdx.x)) * DD * DD;
    #pragma unroll
    for (int i = 0; i < 8; i++) {
        size_t off = base + (size_t)(ty * 8 + i) * DD + tx * 8;
        float4 o0, o1;
        o0.x=acc[i][0]; o0.y=acc[i][1]; o0.z=acc[i][2]; o0.w=acc[i][3];
        o1.x=acc[i][4]; o1.y=acc[i][5]; o1.z=acc[i][6]; o1.w=acc[i][7];
        *(float4*)&part[off]     = o0;
        *(float4*)&part[off + 4] = o1;
    }
}

// ---------------------------------------------------------------------------
// K3c: reductions into d_out
// ---------------------------------------------------------------------------
__global__ void reduce_mem_kernel(const float* __restrict__ part,
                                  const float* __restrict__ memories,
                                  float* __restrict__ out)
{
    int t = blockIdx.x * blockDim.x + threadIdx.x;   // < NH*DD*DD
    int h = t >> 14;
    int rem = t & 16383;
    float s = 0.f;
    #pragma unroll 8
    for (int sl = 0; sl < 64; sl++)
        s += part[((size_t)(h * 64 + sl) << 14) + rem];
    out[OUT_MEM + t] = memories[(size_t)h * DD * DD + rem] + s * (1.f / (float)BQ);
}

__global__ void reduce_norm_kernel(const float* __restrict__ nsum,
                                   const float* __restrict__ mnorms,
                                   float* __restrict__ out)
{
    int t = blockIdx.x * blockDim.x + threadIdx.x;   // < NH*DD
    int h = t >> 7, d = t & 127;
    float s = 0.f;
    for (int b = 0; b < 256; b++)
        s += nsum[(size_t)(h * 256 + b) * DD + d];
    out[OUT_NORM + t] = mnorms[(size_t)h * DD + d] + s * 0.25f;   // / B
}

// ---------------------------------------------------------------------------
extern "C" void kernel_launch(void* const* d_in, const int* in_sizes, int n_in,
                              void* d_out, int out_size)
{
    const float* hs = (const float*)d_in[0];
    const float* Wq = (const float*)d_in[1];
    const float* Wk = (const float*)d_in[2];
    const float* Wv = (const float*)d_in[3];
    const float* Wo = (const float*)d_in[4];
    const float* bw = (const float*)d_in[5];
    const float* mem = (const float*)d_in[6];
    const float* mnm = (const float*)d_in[7];
    float* out = (float*)d_out;

    float *pq, *pk, *pv, *ppart, *pnsum;
    cudaGetSymbolAddress((void**)&pq, g_q);
    cudaGetSymbolAddress((void**)&pk, g_k);
    cudaGetSymbolAddress((void**)&pv, g_v);
    cudaGetSymbolAddress((void**)&ppart, g_part);
    cudaGetSymbolAddress((void**)&pnsum, g_nsum);

    prep_kernel<<<1, 128>>>(bw, mnm);

    dim3 gg(HIDC / BN, BQ / BM);       // (16, 128)
    sgemm_nt<<<gg, 256>>>(hs, Wq, pq, BQ, HIDC, HIDC);
    sgemm_nt<<<gg, 256>>>(hs, Wk, pk, BQ, HIDC, HIDC);
    sgemm_nt<<<gg, 256>>>(hs, Wv, pv, BQ, HIDC, HIDC);

    combined_kernel<<<dim3(BQ / 64, NH), 256>>>(pq, mem, mnm, pq);
    deltav_kernel<<<dim3(BQ / 64, NH), 256>>>(pk, pv, mem, mnm, pnsum);
    memu_kernel<<<dim3(64, NH), 256>>>(pk, pv, ppart);

    reduce_mem_kernel<<<(NH * DD * DD) / 256, 256>>>(ppart, mem, out);
    reduce_norm_kernel<<<(NH * DD) / 256, 256>>>(pnsum, mnm, out);

    sgemm_nt<<<gg, 256>>>(pq, Wo, out, BQ, HIDC, HIDC);
}

// round 6
// speedup vs baseline: 2.4570x; 2.4570x over previous
#include <cuda_runtime.h>
#include <cuda_bf16.h>
#include <math.h>
#include <stdint.h>

// Problem constants
#define BQ   16384          // B*S rows
#define HIDC 2048
#define NH   16
#define DD   128
#define NBANK 4
#define EPSF 1e-6f
#define GK   2048

#define OUT_MEM  ((size_t)BQ * HIDC)
#define OUT_NORM (OUT_MEM + (size_t)NH * DD * DD)

// -------- scratch (static device globals; no runtime allocation) ----------
__device__ float g_q[(size_t)BQ * HIDC];     // q proj, then combined (in place)
__device__ float g_k[(size_t)BQ * HIDC];     // k proj
__device__ float g_v[(size_t)BQ * HIDC];     // v proj, then delta_v (in place)
__device__ float g_part[(size_t)NH * 64 * DD * DD];
__device__ float g_nsum[(size_t)NH * 256 * DD];
__device__ float g_weff[NH][NBANK];

// bf16 hi/lo split buffers
__device__ __nv_bfloat16 g_hs_hi[(size_t)BQ * HIDC];
__device__ __nv_bfloat16 g_hs_lo[(size_t)BQ * HIDC];
__device__ __nv_bfloat16 g_w_hi[4][(size_t)HIDC * HIDC];   // Wq,Wk,Wv,Wo
__device__ __nv_bfloat16 g_w_lo[4][(size_t)HIDC * HIDC];
__device__ __nv_bfloat16 g_cb_hi[(size_t)BQ * HIDC];       // combined hi/lo
__device__ __nv_bfloat16 g_cb_lo[(size_t)BQ * HIDC];

__device__ __forceinline__ float sigf(float x) { return x > 0.f ? x + 1.f : expf(x); }

__device__ __forceinline__ uint32_t smem_to_u32(const void* p) {
    uint32_t a;
    asm("{ .reg .u64 t; cvta.to.shared.u64 t, %1; cvt.u32.u64 %0, t; }" : "=r"(a) : "l"(p));
    return a;
}
#define SW128(off) ((off) ^ (((off) >> 3) & 0x70))

__device__ __forceinline__ void cp_async16(uint32_t saddr, const void* gaddr) {
    asm volatile("cp.async.cg.shared.global [%0], [%1], 16;" :: "r"(saddr), "l"(gaddr));
}
__device__ __forceinline__ void cp_commit() {
    asm volatile("cp.async.commit_group;" ::: "memory");
}
__device__ __forceinline__ void ldsm4(uint32_t* r, uint32_t addr) {
    asm volatile("ldmatrix.sync.aligned.m8n8.x4.shared.b16 {%0,%1,%2,%3}, [%4];"
        : "=r"(r[0]), "=r"(r[1]), "=r"(r[2]), "=r"(r[3]) : "r"(addr));
}
__device__ __forceinline__ void mma_bf16(float* c, const uint32_t* a, const uint32_t* b) {
    asm volatile("mma.sync.aligned.m16n8k16.row.col.f32.bf16.bf16.f32 "
        "{%0,%1,%2,%3}, {%4,%5,%6,%7}, {%8,%9}, {%0,%1,%2,%3};"
        : "+f"(c[0]), "+f"(c[1]), "+f"(c[2]), "+f"(c[3])
        : "r"(a[0]), "r"(a[1]), "r"(a[2]), "r"(a[3]), "r"(b[0]), "r"(b[1]));
}

// ===================== fp32 -> bf16 hi/lo split =====================
__global__ void cvt_split_kernel(const float* __restrict__ x,
                                 __nv_bfloat16* __restrict__ hi,
                                 __nv_bfloat16* __restrict__ lo)
{
    size_t i = ((size_t)blockIdx.x * blockDim.x + threadIdx.x) * 4;
    float4 v = *(const float4*)(x + i);
    __nv_bfloat16 h0 = __float2bfloat16(v.x), h1 = __float2bfloat16(v.y);
    __nv_bfloat16 h2 = __float2bfloat16(v.z), h3 = __float2bfloat16(v.w);
    __nv_bfloat16 l0 = __float2bfloat16(v.x - __bfloat162float(h0));
    __nv_bfloat16 l1 = __float2bfloat16(v.y - __bfloat162float(h1));
    __nv_bfloat16 l2 = __float2bfloat16(v.z - __bfloat162float(h2));
    __nv_bfloat16 l3 = __float2bfloat16(v.w - __bfloat162float(h3));
    __nv_bfloat162* ph = (__nv_bfloat162*)(hi + i);
    __nv_bfloat162* pl = (__nv_bfloat162*)(lo + i);
    ph[0] = __nv_bfloat162(h0, h1); ph[1] = __nv_bfloat162(h2, h3);
    pl[0] = __nv_bfloat162(l0, l1); pl[1] = __nv_bfloat162(l2, l3);
}

// ===================== HMMA GEMM: C[M,N] = A[M,K] @ B[N,K]^T =====================
// bf16 hi/lo 3-pass. Tile 128x128, K-chunk 64, 3-stage cp.async pipeline.
#define CH_BYTES 16384      // one 128x64 bf16 tile
#define STG_BYTES 65536     // 4 tiles (Ah, Al, Bh, Bl)
#define NCHUNK 32           // K / 64
#define HG_SMEM (3 * STG_BYTES + 1024)

__device__ __forceinline__ void load_stage(
    const __nv_bfloat16* __restrict__ Ah, const __nv_bfloat16* __restrict__ Al,
    const __nv_bfloat16* __restrict__ Bh, const __nv_bfloat16* __restrict__ Bl,
    uint32_t sb, int bm, int bn, int k0, int tid)
{
    #pragma unroll
    for (int it = 0; it < 4; it++) {
        int id = tid + it * 256;            // 0..1023
        int r = id >> 3, c = id & 7;
        uint32_t sw = SW128((uint32_t)(r * 128 + c * 16));
        size_t ga = (size_t)(bm + r) * GK + k0 + c * 8;
        size_t gb = (size_t)(bn + r) * GK + k0 + c * 8;
        cp_async16(sb + sw, Ah + ga);
        cp_async16(sb + CH_BYTES + sw, Al + ga);
        cp_async16(sb + 2 * CH_BYTES + sw, Bh + gb);
        cp_async16(sb + 3 * CH_BYTES + sw, Bl + gb);
    }
}

__global__ __launch_bounds__(256, 1)
void hgemm_kernel(const __nv_bfloat16* __restrict__ Ah, const __nv_bfloat16* __restrict__ Al,
                  const __nv_bfloat16* __restrict__ Bh, const __nv_bfloat16* __restrict__ Bl,
                  float* __restrict__ C, int N)
{
    extern __shared__ char smem[];
    uint32_t sraw = smem_to_u32(smem);
    uint32_t sal = (sraw + 1023u) & ~1023u;

    int tid = threadIdx.x;
    int lane = tid & 31, wid = tid >> 5;
    int wm = wid & 3, wn = wid >> 2;         // warp tile 32(m) x 64(n)
    int bm = blockIdx.y * 128;
    int bn = blockIdx.x * 128;

    float acc[2][8][4];
    #pragma unroll
    for (int t = 0; t < 2; t++)
        #pragma unroll
        for (int n = 0; n < 8; n++)
            #pragma unroll
            for (int j = 0; j < 4; j++) acc[t][n][j] = 0.f;

    // prologue: stages 0,1
    load_stage(Ah, Al, Bh, Bl, sal, bm, bn, 0, tid);
    cp_commit();
    load_stage(Ah, Al, Bh, Bl, sal + STG_BYTES, bm, bn, 64, tid);
    cp_commit();

    // precomputed intra-warp ldmatrix offsets (relative to tile base)
    int arow = wm * 32 + (lane & 15);
    uint32_t a_off0 = (uint32_t)(arow * 128 + (lane >> 4) * 16);
    int nrow = wn * 64 + ((lane >> 4) << 3) + (lane & 7);
    uint32_t b_off0 = (uint32_t)(nrow * 128 + ((lane >> 3) & 1) * 16);

    for (int c = 0; c < NCHUNK; c++) {
        asm volatile("cp.async.wait_group 1;" ::: "memory");
        __syncthreads();
        if (c + 2 < NCHUNK) {
            load_stage(Ah, Al, Bh, Bl, sal + ((c + 2) % 3) * STG_BYTES, bm, bn, (c + 2) * 64, tid);
            cp_commit();
        }
        uint32_t sb = sal + (c % 3) * STG_BYTES;

        #pragma unroll
        for (int ks = 0; ks < 4; ks++) {
            uint32_t ah[2][4], al[2][4];
            #pragma unroll
            for (int t = 0; t < 2; t++) {
                uint32_t sw = SW128(a_off0 + t * 16 * 128 + ks * 32);
                ldsm4(ah[t], sb + sw);
                ldsm4(al[t], sb + CH_BYTES + sw);
            }
            #pragma unroll
            for (int ntp = 0; ntp < 4; ntp++) {
                uint32_t sw = SW128(b_off0 + ntp * 16 * 128 + ks * 32);
                uint32_t bh[4], bl[4];
                ldsm4(bh, sb + 2 * CH_BYTES + sw);
                ldsm4(bl, sb + 3 * CH_BYTES + sw);
                #pragma unroll
                for (int t = 0; t < 2; t++) {
                    mma_bf16(acc[t][ntp * 2 + 0], ah[t], bh);
                    mma_bf16(acc[t][ntp * 2 + 0], ah[t], bl);
                    mma_bf16(acc[t][ntp * 2 + 0], al[t], bh);
                    mma_bf16(acc[t][ntp * 2 + 1], ah[t], bh + 2);
                    mma_bf16(acc[t][ntp * 2 + 1], ah[t], bl + 2);
                    mma_bf16(acc[t][ntp * 2 + 1], al[t], bh + 2);
                }
            }
        }
    }

    // epilogue: C frag: c0,c1 at (m = lane>>2, n = (lane&3)*2), c2,c3 at m+8
    #pragma unroll
    for (int t = 0; t < 2; t++) {
        int r0 = bm + wm * 32 + t * 16 + (lane >> 2);
        #pragma unroll
        for (int nt = 0; nt < 8; nt++) {
            int col = bn + wn * 64 + nt * 8 + (lane & 3) * 2;
            float2 v0 = make_float2(acc[t][nt][0], acc[t][nt][1]);
            float2 v1 = make_float2(acc[t][nt][2], acc[t][nt][3]);
            *(float2*)&C[(size_t)r0 * N + col]       = v0;
            *(float2*)&C[(size_t)(r0 + 8) * N + col] = v1;
        }
    }
}

// ===================== K0: softmax of bank weights + active flags =====================
__global__ void prep_kernel(const float* __restrict__ bw, const float* __restrict__ mn) {
    __shared__ float bsum[NBANK];
    int tid = threadIdx.x;
    int w = tid >> 5, lane = tid & 31;
    if (w < NBANK) {
        float s = 0.f;
        for (int i = lane; i < NH * DD; i += 32) s += mn[w * NH * DD + i];
        #pragma unroll
        for (int o = 16; o; o >>= 1) s += __shfl_down_sync(0xffffffffu, s, o);
        if (lane == 0) bsum[w] = s;
    }
    __syncthreads();
    if (tid < NH) {
        float x0 = bw[tid * 4 + 0], x1 = bw[tid * 4 + 1];
        float x2 = bw[tid * 4 + 2], x3 = bw[tid * 4 + 3];
        float m = fmaxf(fmaxf(x0, x1), fmaxf(x2, x3));
        float e0 = expf(x0 - m), e1 = expf(x1 - m), e2 = expf(x2 - m), e3 = expf(x3 - m);
        float inv = 1.f / (e0 + e1 + e2 + e3);
        g_weff[tid][0] = e0 * inv * (bsum[0] >= EPSF ? 1.f : 0.f);
        g_weff[tid][1] = e1 * inv * (bsum[1] >= EPSF ? 1.f : 0.f);
        g_weff[tid][2] = e2 * inv * (bsum[2] >= EPSF ? 1.f : 0.f);
        g_weff[tid][3] = e3 * inv * (bsum[3] >= EPSF ? 1.f : 0.f);
    }
}

// ===================== K2: bank retrieval + weighted combine =====================
__global__ __launch_bounds__(256) void combined_kernel(
    const float* __restrict__ q, const float* __restrict__ memories,
    const float* __restrict__ mnorms, float* __restrict__ comb)
{
    __shared__ float sq[64][DD + 1];
    __shared__ float ms[16][DD + 4];
    __shared__ float mn[NBANK][DD];
    __shared__ float csm[64][NBANK];
    int h = blockIdx.y;
    int row0 = blockIdx.x * 64;
    int tid = threadIdx.x;

    #pragma unroll
    for (int it = 0; it < 8; it++) {
        int id = tid + it * 256;
        int r = id >> 5, c4 = id & 31;
        float4 v = *(const float4*)&q[(size_t)(row0 + r) * HIDC + h * DD + c4 * 4];
        sq[r][c4 * 4 + 0] = sigf(v.x); sq[r][c4 * 4 + 1] = sigf(v.y);
        sq[r][c4 * 4 + 2] = sigf(v.z); sq[r][c4 * 4 + 3] = sigf(v.w);
    }
    #pragma unroll
    for (int it = 0; it < 2; it++) {
        int id = tid + it * 256;
        int n = id >> 7, d = id & 127;
        mn[n][d] = mnorms[(size_t)(n * NH + h) * DD + d];
    }
    __syncthreads();
    {
        int row = tid >> 2, n = tid & 3;
        float s = 0.f;
        #pragma unroll 8
        for (int d = 0; d < DD; d++) s += sq[row][d] * mn[n][d];
        csm[row][n] = g_weff[h][n] / fmaxf(s, EPSF);
    }
    __syncthreads();

    int tx = tid & 15, ty = tid >> 4;
    float fin[4][8];
    #pragma unroll
    for (int i = 0; i < 4; i++)
        #pragma unroll
        for (int j = 0; j < 8; j++) fin[i][j] = 0.f;

    for (int n = 0; n < NBANK; n++) {
        float acc[4][8];
        #pragma unroll
        for (int i = 0; i < 4; i++)
            #pragma unroll
            for (int j = 0; j < 8; j++) acc[i][j] = 0.f;
        const float* mbase = memories + (size_t)(n * NH + h) * DD * DD;
        for (int dc = 0; dc < 8; dc++) {
            #pragma unroll
            for (int it = 0; it < 2; it++) {
                int id = tid + it * 256;
                int kr = id >> 5, c4 = id & 31;
                float4 v = *(const float4*)&mbase[(size_t)(dc * 16 + kr) * DD + c4 * 4];
                *(float4*)&ms[kr][c4 * 4] = v;
            }
            __syncthreads();
            #pragma unroll
            for (int kk = 0; kk < 16; kk++) {
                int d = dc * 16 + kk;
                float a0 = sq[ty * 4 + 0][d], a1 = sq[ty * 4 + 1][d];
                float a2 = sq[ty * 4 + 2][d], a3 = sq[ty * 4 + 3][d];
                float4 b0 = *(float4*)&ms[kk][tx * 8];
                float4 b1 = *(float4*)&ms[kk][tx * 8 + 4];
                float b[8] = {b0.x,b0.y,b0.z,b0.w,b1.x,b1.y,b1.z,b1.w};
                #pragma unroll
                for (int j = 0; j < 8; j++) {
                    acc[0][j] = fmaf(a0, b[j], acc[0][j]);
                    acc[1][j] = fmaf(a1, b[j], acc[1][j]);
                    acc[2][j] = fmaf(a2, b[j], acc[2][j]);
                    acc[3][j] = fmaf(a3, b[j], acc[3][j]);
                }
            }
            __syncthreads();
        }
        #pragma unroll
        for (int i = 0; i < 4; i++) {
            float c = csm[ty * 4 + i][n];
            #pragma unroll
            for (int j = 0; j < 8; j++) fin[i][j] = fmaf(c, acc[i][j], fin[i][j]);
        }
    }
    #pragma unroll
    for (int i = 0; i < 4; i++) {
        float4 o0, o1;
        o0.x=fin[i][0]; o0.y=fin[i][1]; o0.z=fin[i][2]; o0.w=fin[i][3];
        o1.x=fin[i][4]; o1.y=fin[i][5]; o1.z=fin[i][6]; o1.w=fin[i][7];
        size_t off = (size_t)(row0 + ty * 4 + i) * HIDC + h * DD + tx * 8;
        *(float4*)&comb[off]     = o0;
        *(float4*)&comb[off + 4] = o1;
    }
}

// ===================== K3a: delta_v =====================
__global__ __launch_bounds__(256) void deltav_kernel(
    const float* __restrict__ k, float* __restrict__ v,
    const float* __restrict__ memories, const float* __restrict__ mnorms,
    float* __restrict__ nsum)
{
    __shared__ float sk[64][DD + 1];
    __shared__ float ms[16][DD + 4];
    __shared__ float mn0[DD];
    __shared__ float kn[64];
    __shared__ float csum[2][DD];
    int h = blockIdx.y;
    int row0 = blockIdx.x * 64;
    int tid = threadIdx.x;

    #pragma unroll
    for (int it = 0; it < 8; it++) {
        int id = tid + it * 256;
        int r = id >> 5, c4 = id & 31;
        float4 vv = *(const float4*)&k[(size_t)(row0 + r) * HIDC + h * DD + c4 * 4];
        sk[r][c4 * 4 + 0] = sigf(vv.x); sk[r][c4 * 4 + 1] = sigf(vv.y);
        sk[r][c4 * 4 + 2] = sigf(vv.z); sk[r][c4 * 4 + 3] = sigf(vv.w);
    }
    if (tid < DD) mn0[tid] = mnorms[(size_t)h * DD + tid];
    __syncthreads();

    if (tid < 64) {
        float s = 0.f;
        #pragma unroll 8
        for (int d = 0; d < DD; d++) s += sk[tid][d] * mn0[d];
        kn[tid] = fmaxf(s, EPSF);
    }
    {
        int col = tid & 127, half = tid >> 7;
        float s = 0.f;
        #pragma unroll 8
        for (int r = half * 32; r < half * 32 + 32; r++) s += sk[r][col];
        csum[half][col] = s;
    }
    __syncthreads();
    if (tid < DD)
        nsum[(size_t)(h * 256 + blockIdx.x) * DD + tid] = csum[0][tid] + csum[1][tid];

    int tx = tid & 15, ty = tid >> 4;
    float acc[4][8];
    #pragma unroll
    for (int i = 0; i < 4; i++)
        #pragma unroll
        for (int j = 0; j < 8; j++) acc[i][j] = 0.f;

    const float* mbase = memories + (size_t)h * DD * DD;
    for (int dc = 0; dc < 8; dc++) {
        #pragma unroll
        for (int it = 0; it < 2; it++) {
            int id = tid + it * 256;
            int kr = id >> 5, c4 = id & 31;
            float4 vv = *(const float4*)&mbase[(size_t)(dc * 16 + kr) * DD + c4 * 4];
            *(float4*)&ms[kr][c4 * 4] = vv;
        }
        __syncthreads();
        #pragma unroll
        for (int kk = 0; kk < 16; kk++) {
            int d = dc * 16 + kk;
            float a0 = sk[ty * 4 + 0][d], a1 = sk[ty * 4 + 1][d];
            float a2 = sk[ty * 4 + 2][d], a3 = sk[ty * 4 + 3][d];
            float4 b0 = *(float4*)&ms[kk][tx * 8];
            float4 b1 = *(float4*)&ms[kk][tx * 8 + 4];
            float b[8] = {b0.x,b0.y,b0.z,b0.w,b1.x,b1.y,b1.z,b1.w};
            #pragma unroll
            for (int j = 0; j < 8; j++) {
                acc[0][j] = fmaf(a0, b[j], acc[0][j]);
                acc[1][j] = fmaf(a1, b[j], acc[1][j]);
                acc[2][j] = fmaf(a2, b[j], acc[2][j]);
                acc[3][j] = fmaf(a3, b[j], acc[3][j]);
            }
        }
        __syncthreads();
    }
    #pragma unroll
    for (int i = 0; i < 4; i++) {
        float inv = 1.f / kn[ty * 4 + i];
        size_t off = (size_t)(row0 + ty * 4 + i) * HIDC + h * DD + tx * 8;
        float4 v0 = *(float4*)&v[off];
        float4 v1 = *(float4*)&v[off + 4];
        v0.x -= acc[i][0]*inv; v0.y -= acc[i][1]*inv; v0.z -= acc[i][2]*inv; v0.w -= acc[i][3]*inv;
        v1.x -= acc[i][4]*inv; v1.y -= acc[i][5]*inv; v1.z -= acc[i][6]*inv; v1.w -= acc[i][7]*inv;
        *(float4*)&v[off]     = v0;
        *(float4*)&v[off + 4] = v1;
    }
}

// ===================== K3b: mem_update split-K =====================
__global__ __launch_bounds__(256) void memu_kernel(
    const float* __restrict__ k, const float* __restrict__ dv,
    float* __restrict__ part)
{
    __shared__ float sk[16][DD + 4];
    __shared__ float sv[16][DD + 4];
    int h = blockIdx.y;
    int r0 = blockIdx.x * 256;
    int tid = threadIdx.x;
    int tx = tid & 15, ty = tid >> 4;

    float acc[8][8];
    #pragma unroll
    for (int i = 0; i < 8; i++)
        #pragma unroll
        for (int j = 0; j < 8; j++) acc[i][j] = 0.f;

    for (int rc = 0; rc < 16; rc++) {
        #pragma unroll
        for (int it = 0; it < 2; it++) {
            int id = tid + it * 256;
            int rr = id >> 5, c4 = id & 31;
            size_t off = (size_t)(r0 + rc * 16 + rr) * HIDC + h * DD + c4 * 4;
            float4 kv = *(const float4*)&k[off];
            sk[rr][c4*4+0] = sigf(kv.x); sk[rr][c4*4+1] = sigf(kv.y);
            sk[rr][c4*4+2] = sigf(kv.z); sk[rr][c4*4+3] = sigf(kv.w);
            float4 vv = *(const float4*)&dv[off];
            *(float4*)&sv[rr][c4 * 4] = vv;
        }
        __syncthreads();
        #pragma unroll
        for (int rr = 0; rr < 16; rr++) {
            float4 a0 = *(float4*)&sk[rr][ty * 8];
            float4 a1 = *(float4*)&sk[rr][ty * 8 + 4];
            float a[8] = {a0.x,a0.y,a0.z,a0.w,a1.x,a1.y,a1.z,a1.w};
            float4 b0 = *(float4*)&sv[rr][tx * 8];
            float4 b1 = *(float4*)&sv[rr][tx * 8 + 4];
            float b[8] = {b0.x,b0.y,b0.z,b0.w,b1.x,b1.y,b1.z,b1.w};
            #pragma unroll
            for (int i = 0; i < 8; i++)
                #pragma unroll
                for (int j = 0; j < 8; j++)
                    acc[i][j] = fmaf(a[i], b[j], acc[i][j]);
        }
        __syncthreads();
    }
    size_t base = ((size_t)(h * 64 + blockIdx.x)) * DD * DD;
    #pragma unroll
    for (int i = 0; i < 8; i++) {
        size_t off = base + (size_t)(ty * 8 + i) * DD + tx * 8;
        float4 o0, o1;
        o0.x=acc[i][0]; o0.y=acc[i][1]; o0.z=acc[i][2]; o0.w=acc[i][3];
        o1.x=acc[i][4]; o1.y=acc[i][5]; o1.z=acc[i][6]; o1.w=acc[i][7];
        *(float4*)&part[off]     = o0;
        *(float4*)&part[off + 4] = o1;
    }
}

// ===================== K3c: reductions =====================
__global__ void reduce_mem_kernel(const float* __restrict__ part,
                                  const float* __restrict__ memories,
                                  float* __restrict__ out)
{
    int t = blockIdx.x * blockDim.x + threadIdx.x;
    int h = t >> 14;
    int rem = t & 16383;
    float s = 0.f;
    #pragma unroll 8
    for (int sl = 0; sl < 64; sl++)
        s += part[((size_t)(h * 64 + sl) << 14) + rem];
    out[OUT_MEM + t] = memories[(size_t)h * DD * DD + rem] + s * (1.f / (float)BQ);
}

__global__ void reduce_norm_kernel(const float* __restrict__ nsum,
                                   const float* __restrict__ mnorms,
                                   float* __restrict__ out)
{
    int t = blockIdx.x * blockDim.x + threadIdx.x;
    int h = t >> 7, d = t & 127;
    float s = 0.f;
    for (int b = 0; b < 256; b++)
        s += nsum[(size_t)(h * 256 + b) * DD + d];
    out[OUT_NORM + t] = mnorms[(size_t)h * DD + d] + s * 0.25f;
}

// ---------------------------------------------------------------------------
extern "C" void kernel_launch(void* const* d_in, const int* in_sizes, int n_in,
                              void* d_out, int out_size)
{
    const float* hs = (const float*)d_in[0];
    const float* Wq = (const float*)d_in[1];
    const float* Wk = (const float*)d_in[2];
    const float* Wv = (const float*)d_in[3];
    const float* Wo = (const float*)d_in[4];
    const float* bw = (const float*)d_in[5];
    const float* mem = (const float*)d_in[6];
    const float* mnm = (const float*)d_in[7];
    float* out = (float*)d_out;

    float *pq, *pk, *pv, *ppart, *pnsum;
    __nv_bfloat16 *hsh, *hsl, *wh, *wl, *cbh, *cbl;
    cudaGetSymbolAddress((void**)&pq, g_q);
    cudaGetSymbolAddress((void**)&pk, g_k);
    cudaGetSymbolAddress((void**)&pv, g_v);
    cudaGetSymbolAddress((void**)&ppart, g_part);
    cudaGetSymbolAddress((void**)&pnsum, g_nsum);
    cudaGetSymbolAddress((void**)&hsh, g_hs_hi);
    cudaGetSymbolAddress((void**)&hsl, g_hs_lo);
    cudaGetSymbolAddress((void**)&wh, g_w_hi);
    cudaGetSymbolAddress((void**)&wl, g_w_lo);
    cudaGetSymbolAddress((void**)&cbh, g_cb_hi);
    cudaGetSymbolAddress((void**)&cbl, g_cb_lo);

    static int smem_set = 0;
    if (!smem_set) {
        cudaFuncSetAttribute(hgemm_kernel, cudaFuncAttributeMaxDynamicSharedMemorySize, HG_SMEM);
        smem_set = 1;
    }

    prep_kernel<<<1, 128>>>(bw, mnm);

    // fp32 -> bf16 hi/lo splits
    const size_t WSZ = (size_t)HIDC * HIDC;
    cvt_split_kernel<<<(BQ * (size_t)HIDC) / 4 / 256, 256>>>(hs, hsh, hsl);
    cvt_split_kernel<<<WSZ / 4 / 256, 256>>>(Wq, wh + 0 * WSZ, wl + 0 * WSZ);
    cvt_split_kernel<<<WSZ / 4 / 256, 256>>>(Wk, wh + 1 * WSZ, wl + 1 * WSZ);
    cvt_split_kernel<<<WSZ / 4 / 256, 256>>>(Wv, wh + 2 * WSZ, wl + 2 * WSZ);
    cvt_split_kernel<<<WSZ / 4 / 256, 256>>>(Wo, wh + 3 * WSZ, wl + 3 * WSZ);

    dim3 gg(HIDC / 128, BQ / 128);   // (16, 128)
    hgemm_kernel<<<gg, 256, HG_SMEM>>>(hsh, hsl, wh + 0 * WSZ, wl + 0 * WSZ, pq, HIDC);
    hgemm_kernel<<<gg, 256, HG_SMEM>>>(hsh, hsl, wh + 1 * WSZ, wl + 1 * WSZ, pk, HIDC);
    hgemm_kernel<<<gg, 256, HG_SMEM>>>(hsh, hsl, wh + 2 * WSZ, wl + 2 * WSZ, pv, HIDC);

    combined_kernel<<<dim3(BQ / 64, NH), 256>>>(pq, mem, mnm, pq);
    deltav_kernel<<<dim3(BQ / 64, NH), 256>>>(pk, pv, mem, mnm, pnsum);
    memu_kernel<<<dim3(64, NH), 256>>>(pk, pv, ppart);

    reduce_mem_kernel<<<(NH * DD * DD) / 256, 256>>>(ppart, mem, out);
    reduce_norm_kernel<<<(NH * DD) / 256, 256>>>(pnsum, mnm, out);

    // combined -> hi/lo, then output GEMM
    cvt_split_kernel<<<(BQ * (size_t)HIDC) / 4 / 256, 256>>>(pq, cbh, cbl);
    hgemm_kernel<<<gg, 256, HG_SMEM>>>(cbh, cbl, wh + 3 * WSZ, wl + 3 * WSZ, out, HIDC);
}

// round 7
// speedup vs baseline: 2.9704x; 1.2090x over previous
#include <cuda_runtime.h>
#include <cuda_bf16.h>
#include <math.h>
#include <stdint.h>

// Problem constants
#define BQ   16384          // B*S rows
#define HIDC 2048
#define NH   16
#define DD   128
#define NBANK 4
#define EPSF 1e-6f
#define GK   2048

#define OUT_MEM  ((size_t)BQ * HIDC)
#define OUT_NORM (OUT_MEM + (size_t)NH * DD * DD)

// -------- scratch (static device globals; no runtime allocation) ----------
__device__ float g_q[(size_t)BQ * HIDC];     // q proj, then combined (in place)
__device__ float g_k[(size_t)BQ * HIDC];     // k proj
__device__ float g_v[(size_t)BQ * HIDC];     // v proj, then delta_v (in place)
__device__ float g_part[(size_t)NH * 64 * DD * DD];
__device__ float g_nsum[(size_t)NH * 256 * DD];
__device__ float g_weff[NH][NBANK];

// bf16 hi/lo split buffers
__device__ __nv_bfloat16 g_hs_hi[(size_t)BQ * HIDC];
__device__ __nv_bfloat16 g_hs_lo[(size_t)BQ * HIDC];
__device__ __nv_bfloat16 g_w_hi[4][(size_t)HIDC * HIDC];   // Wq,Wk,Wv,Wo
__device__ __nv_bfloat16 g_w_lo[4][(size_t)HIDC * HIDC];
__device__ __nv_bfloat16 g_cb_hi[(size_t)BQ * HIDC];       // combined hi/lo
__device__ __nv_bfloat16 g_cb_lo[(size_t)BQ * HIDC];

// pre-swizzled transposed memories (B-operand layout) + norm tiles
__device__ __nv_bfloat16 g_mTh[(size_t)NBANK * NH * DD * DD];
__device__ __nv_bfloat16 g_mTl[(size_t)NBANK * NH * DD * DD];
__device__ __nv_bfloat16 g_nTh[(size_t)NH * 1024];
__device__ __nv_bfloat16 g_nTl[(size_t)NH * 1024];

__device__ __forceinline__ float sigf(float x) { return x > 0.f ? x + 1.f : expf(x); }

__device__ __forceinline__ uint32_t smem_to_u32(const void* p) {
    uint32_t a;
    asm("{ .reg .u64 t; cvta.to.shared.u64 t, %1; cvt.u32.u64 %0, t; }" : "=r"(a) : "l"(p));
    return a;
}
#define SW128(off) ((off) ^ (((off) >> 3) & 0x70))

__device__ __forceinline__ void cp_async16(uint32_t saddr, const void* gaddr) {
    asm volatile("cp.async.cg.shared.global [%0], [%1], 16;" :: "r"(saddr), "l"(gaddr));
}
__device__ __forceinline__ void cp_commit() {
    asm volatile("cp.async.commit_group;" ::: "memory");
}
__device__ __forceinline__ void ldsm4(uint32_t* r, uint32_t addr) {
    asm volatile("ldmatrix.sync.aligned.m8n8.x4.shared.b16 {%0,%1,%2,%3}, [%4];"
        : "=r"(r[0]), "=r"(r[1]), "=r"(r[2]), "=r"(r[3]) : "r"(addr));
}
__device__ __forceinline__ void ldsm2(uint32_t* r, uint32_t addr) {
    asm volatile("ldmatrix.sync.aligned.m8n8.x2.shared.b16 {%0,%1}, [%2];"
        : "=r"(r[0]), "=r"(r[1]) : "r"(addr));
}
__device__ __forceinline__ void mma_bf16(float* c, const uint32_t* a, const uint32_t* b) {
    asm volatile("mma.sync.aligned.m16n8k16.row.col.f32.bf16.bf16.f32 "
        "{%0,%1,%2,%3}, {%4,%5,%6,%7}, {%8,%9}, {%0,%1,%2,%3};"
        : "+f"(c[0]), "+f"(c[1]), "+f"(c[2]), "+f"(c[3])
        : "r"(a[0]), "r"(a[1]), "r"(a[2]), "r"(a[3]), "r"(b[0]), "r"(b[1]));
}

// ===================== fp32 -> bf16 hi/lo split =====================
__global__ void cvt_split_kernel(const float* __restrict__ x,
                                 __nv_bfloat16* __restrict__ hi,
                                 __nv_bfloat16* __restrict__ lo)
{
    size_t i = ((size_t)blockIdx.x * blockDim.x + threadIdx.x) * 4;
    float4 v = *(const float4*)(x + i);
    __nv_bfloat16 h0 = __float2bfloat16(v.x), h1 = __float2bfloat16(v.y);
    __nv_bfloat16 h2 = __float2bfloat16(v.z), h3 = __float2bfloat16(v.w);
    __nv_bfloat16 l0 = __float2bfloat16(v.x - __bfloat162float(h0));
    __nv_bfloat16 l1 = __float2bfloat16(v.y - __bfloat162float(h1));
    __nv_bfloat16 l2 = __float2bfloat16(v.z - __bfloat162float(h2));
    __nv_bfloat16 l3 = __float2bfloat16(v.w - __bfloat162float(h3));
    __nv_bfloat162* ph = (__nv_bfloat162*)(hi + i);
    __nv_bfloat162* pl = (__nv_bfloat162*)(lo + i);
    ph[0] = __nv_bfloat162(h0, h1); ph[1] = __nv_bfloat162(h2, h3);
    pl[0] = __nv_bfloat162(l0, l1); pl[1] = __nv_bfloat162(l2, l3);
}

// ===================== HMMA GEMM: C[M,N] = A[M,K] @ B[N,K]^T =====================
#define CH_BYTES 16384      // one 128x64 bf16 tile
#define STG_BYTES 65536     // 4 tiles (Ah, Al, Bh, Bl)
#define NCHUNK 32           // K / 64
#define HG_SMEM (3 * STG_BYTES + 1024)

__device__ __forceinline__ void load_stage(
    const __nv_bfloat16* __restrict__ Ah, const __nv_bfloat16* __restrict__ Al,
    const __nv_bfloat16* __restrict__ Bh, const __nv_bfloat16* __restrict__ Bl,
    uint32_t sb, int bm, int bn, int k0, int tid)
{
    #pragma unroll
    for (int it = 0; it < 4; it++) {
        int id = tid + it * 256;            // 0..1023
        int r = id >> 3, c = id & 7;
        uint32_t sw = SW128((uint32_t)(r * 128 + c * 16));
        size_t ga = (size_t)(bm + r) * GK + k0 + c * 8;
        size_t gb = (size_t)(bn + r) * GK + k0 + c * 8;
        cp_async16(sb + sw, Ah + ga);
        cp_async16(sb + CH_BYTES + sw, Al + ga);
        cp_async16(sb + 2 * CH_BYTES + sw, Bh + gb);
        cp_async16(sb + 3 * CH_BYTES + sw, Bl + gb);
    }
}

__global__ __launch_bounds__(256, 1)
void hgemm_kernel(const __nv_bfloat16* __restrict__ Ah, const __nv_bfloat16* __restrict__ Al,
                  const __nv_bfloat16* __restrict__ Bh, const __nv_bfloat16* __restrict__ Bl,
                  float* __restrict__ C, int N)
{
    extern __shared__ char smem[];
    uint32_t sraw = smem_to_u32(smem);
    uint32_t sal = (sraw + 1023u) & ~1023u;

    int tid = threadIdx.x;
    int lane = tid & 31, wid = tid >> 5;
    int wm = wid & 3, wn = wid >> 2;         // warp tile 32(m) x 64(n)
    int bm = blockIdx.y * 128;
    int bn = blockIdx.x * 128;

    float acc[2][8][4];
    #pragma unroll
    for (int t = 0; t < 2; t++)
        #pragma unroll
        for (int n = 0; n < 8; n++)
            #pragma unroll
            for (int j = 0; j < 4; j++) acc[t][n][j] = 0.f;

    load_stage(Ah, Al, Bh, Bl, sal, bm, bn, 0, tid);
    cp_commit();
    load_stage(Ah, Al, Bh, Bl, sal + STG_BYTES, bm, bn, 64, tid);
    cp_commit();

    int arow = wm * 32 + (lane & 15);
    uint32_t a_off0 = (uint32_t)(arow * 128 + (lane >> 4) * 16);
    int nrow = wn * 64 + ((lane >> 4) << 3) + (lane & 7);
    uint32_t b_off0 = (uint32_t)(nrow * 128 + ((lane >> 3) & 1) * 16);

    for (int c = 0; c < NCHUNK; c++) {
        asm volatile("cp.async.wait_group 1;" ::: "memory");
        __syncthreads();
        if (c + 2 < NCHUNK) {
            load_stage(Ah, Al, Bh, Bl, sal + ((c + 2) % 3) * STG_BYTES, bm, bn, (c + 2) * 64, tid);
            cp_commit();
        }
        uint32_t sb = sal + (c % 3) * STG_BYTES;

        #pragma unroll
        for (int ks = 0; ks < 4; ks++) {
            uint32_t ah[2][4], al[2][4];
            #pragma unroll
            for (int t = 0; t < 2; t++) {
                uint32_t sw = SW128(a_off0 + t * 16 * 128 + ks * 32);
                ldsm4(ah[t], sb + sw);
                ldsm4(al[t], sb + CH_BYTES + sw);
            }
            #pragma unroll
            for (int ntp = 0; ntp < 4; ntp++) {
                uint32_t sw = SW128(b_off0 + ntp * 16 * 128 + ks * 32);
                uint32_t bh[4], bl[4];
                ldsm4(bh, sb + 2 * CH_BYTES + sw);
                ldsm4(bl, sb + 3 * CH_BYTES + sw);
                #pragma unroll
                for (int t = 0; t < 2; t++) {
                    mma_bf16(acc[t][ntp * 2 + 0], ah[t], bh);
                    mma_bf16(acc[t][ntp * 2 + 0], ah[t], bl);
                    mma_bf16(acc[t][ntp * 2 + 0], al[t], bh);
                    mma_bf16(acc[t][ntp * 2 + 1], ah[t], bh + 2);
                    mma_bf16(acc[t][ntp * 2 + 1], ah[t], bl + 2);
                    mma_bf16(acc[t][ntp * 2 + 1], al[t], bh + 2);
                }
            }
        }
    }

    #pragma unroll
    for (int t = 0; t < 2; t++) {
        int r0 = bm + wm * 32 + t * 16 + (lane >> 2);
        #pragma unroll
        for (int nt = 0; nt < 8; nt++) {
            int col = bn + wn * 64 + nt * 8 + (lane & 3) * 2;
            float2 v0 = make_float2(acc[t][nt][0], acc[t][nt][1]);
            float2 v1 = make_float2(acc[t][nt][2], acc[t][nt][3]);
            *(float2*)&C[(size_t)r0 * N + col]       = v0;
            *(float2*)&C[(size_t)(r0 + 8) * N + col] = v1;
        }
    }
}

// ===================== K0: softmax of bank weights + active flags =====================
__global__ void prep_kernel(const float* __restrict__ bw, const float* __restrict__ mn) {
    __shared__ float bsum[NBANK];
    int tid = threadIdx.x;
    int w = tid >> 5, lane = tid & 31;
    if (w < NBANK) {
        float s = 0.f;
        for (int i = lane; i < NH * DD; i += 32) s += mn[w * NH * DD + i];
        #pragma unroll
        for (int o = 16; o; o >>= 1) s += __shfl_down_sync(0xffffffffu, s, o);
        if (lane == 0) bsum[w] = s;
    }
    __syncthreads();
    if (tid < NH) {
        float x0 = bw[tid * 4 + 0], x1 = bw[tid * 4 + 1];
        float x2 = bw[tid * 4 + 2], x3 = bw[tid * 4 + 3];
        float m = fmaxf(fmaxf(x0, x1), fmaxf(x2, x3));
        float e0 = expf(x0 - m), e1 = expf(x1 - m), e2 = expf(x2 - m), e3 = expf(x3 - m);
        float inv = 1.f / (e0 + e1 + e2 + e3);
        g_weff[tid][0] = e0 * inv * (bsum[0] >= EPSF ? 1.f : 0.f);
        g_weff[tid][1] = e1 * inv * (bsum[1] >= EPSF ? 1.f : 0.f);
        g_weff[tid][2] = e2 * inv * (bsum[2] >= EPSF ? 1.f : 0.f);
        g_weff[tid][3] = e3 * inv * (bsum[3] >= EPSF ? 1.f : 0.f);
    }
}

// ===================== prep2: memories -> transposed, split, pre-swizzled =====================
// B-operand layout per (n,h): 2 K-chunks x [128 e-rows x 64 d-cols], SW128 within chunk.
__global__ void prep2_kernel(const float* __restrict__ mem,
                             __nv_bfloat16* __restrict__ mTh, __nv_bfloat16* __restrict__ mTl)
{
    int nh = blockIdx.x;     // 0..63
    const float* src = mem + (size_t)nh * 16384;
    __nv_bfloat16* dh = mTh + (size_t)nh * 16384;
    __nv_bfloat16* dl = mTl + (size_t)nh * 16384;
    for (int i = threadIdx.x; i < 16384; i += 256) {
        int d = i >> 7, e = i & 127;
        float v = src[d * 128 + e];
        __nv_bfloat16 hi = __float2bfloat16(v);
        __nv_bfloat16 lo = __float2bfloat16(v - __bfloat162float(hi));
        uint32_t off = ((uint32_t)(d >> 6) << 13) +
                       (SW128((uint32_t)(e * 128 + (d & 63) * 2)) >> 1);
        dh[off] = hi; dl[off] = lo;
    }
}

// norm tile per h: 2 chunks x [8 rows x 64 d-cols]; rows 0..3 = mnorm bank n, 4..7 zero.
__global__ void normt_kernel(const float* __restrict__ mnm,
                             __nv_bfloat16* __restrict__ nTh, __nv_bfloat16* __restrict__ nTl)
{
    int h = blockIdx.x;
    for (int i = threadIdx.x; i < 1024; i += 256) {
        int nr = i >> 7, d = i & 127;
        float v = (nr < NBANK) ? mnm[(size_t)(nr * NH + h) * DD + d] : 0.f;
        __nv_bfloat16 hi = __float2bfloat16(v);
        __nv_bfloat16 lo = __float2bfloat16(v - __bfloat162float(hi));
        uint32_t off = ((uint32_t)(d >> 6) << 9) +
                       (SW128((uint32_t)(nr * 128 + (d & 63) * 2)) >> 1);
        nTh[h * 1024 + off] = hi; nTl[h * 1024 + off] = lo;
    }
}

// ===================== HMMA combined / deltav =====================
// smem layout (bytes from 1024-aligned base):
#define CB_SAH   0            // sigma hi: 2 chunks x 16KB
#define CB_SAL   32768        // sigma lo
#define CB_SB    65536        // bank buffers: buf*65536, each = hi 32KB + lo 32KB
#define CB_SNTH  196608       // norm tile hi (2KB)
#define CB_SNTL  198656       // norm tile lo (2KB)
#define CB_SNORM 200704       // 128 x 4 floats
#define CB_SCOEF 202752       // 128 x 4 floats
#define CB_SSUM  204800       // 128 x 2 floats (deltav col sums)
#define CB_SMEM  207872

// convert one 128x128 fp32 tile (sigf applied) into sA hi/lo smem tiles
__device__ __forceinline__ void sigma_to_smem(const float* __restrict__ src, int row0, int h,
                                              char* sb, int tid)
{
    #pragma unroll
    for (int i = 0; i < 16; i++) {
        int id = tid + i * 256;          // 0..4095 float4s
        int r = id >> 5, c4 = id & 31;
        float4 v = *(const float4*)&src[(size_t)(row0 + r) * HIDC + h * DD + c4 * 4];
        float s0 = sigf(v.x), s1 = sigf(v.y), s2 = sigf(v.z), s3 = sigf(v.w);
        __nv_bfloat16 h0 = __float2bfloat16(s0), h1 = __float2bfloat16(s1);
        __nv_bfloat16 h2 = __float2bfloat16(s2), h3 = __float2bfloat16(s3);
        __nv_bfloat16 l0 = __float2bfloat16(s0 - __bfloat162float(h0));
        __nv_bfloat16 l1 = __float2bfloat16(s1 - __bfloat162float(h1));
        __nv_bfloat16 l2 = __float2bfloat16(s2 - __bfloat162float(h2));
        __nv_bfloat16 l3 = __float2bfloat16(s3 - __bfloat162float(h3));
        int d0 = c4 * 4;
        uint32_t off = (uint32_t)((d0 >> 6) * 16384) + SW128((uint32_t)(r * 128 + (d0 & 63) * 2));
        *(__nv_bfloat162*)(sb + CB_SAH + off)     = __nv_bfloat162(h0, h1);
        *(__nv_bfloat162*)(sb + CB_SAH + off + 4) = __nv_bfloat162(h2, h3);
        *(__nv_bfloat162*)(sb + CB_SAL + off)     = __nv_bfloat162(l0, l1);
        *(__nv_bfloat162*)(sb + CB_SAL + off + 4) = __nv_bfloat162(l2, l3);
    }
}

// norm MMA chain (warps with wn==0): fills sNorm[128][4]
__device__ __forceinline__ void norm_mma(uint32_t sal, char* sb, int wm, int lane)
{
    float nc[2][4];
    #pragma unroll
    for (int t = 0; t < 2; t++)
        #pragma unroll
        for (int j = 0; j < 4; j++) nc[t][j] = 0.f;
    #pragma unroll
    for (int ks = 0; ks < 8; ks++) {
        uint32_t ah[2][4], al[2][4];
        #pragma unroll
        for (int t = 0; t < 2; t++) {
            uint32_t aaddr = sal + CB_SAH + (ks >> 2) * 16384 +
                SW128((uint32_t)((wm * 32 + t * 16 + (lane & 15)) * 128 + (ks & 3) * 32 + (lane >> 4) * 16));
            ldsm4(ah[t], aaddr);
            ldsm4(al[t], aaddr + 32768);
        }
        uint32_t bh[2], bl[2];
        uint32_t naddr = sal + CB_SNTH + (ks >> 2) * 1024 +
            SW128((uint32_t)((lane & 7) * 128 + (ks & 3) * 32 + ((lane >> 3) & 1) * 16));
        ldsm2(bh, naddr);
        ldsm2(bl, naddr + 2048);
        #pragma unroll
        for (int t = 0; t < 2; t++) {
            mma_bf16(nc[t], ah[t], bh);
            mma_bf16(nc[t], al[t], bh);
            mma_bf16(nc[t], ah[t], bl);
        }
    }
    float* sN = (float*)(sb + CB_SNORM);
    if ((lane & 3) < 2) {
        #pragma unroll
        for (int t = 0; t < 2; t++) {
            int rr = wm * 32 + t * 16 + (lane >> 2);
            sN[rr * 4 + (lane & 3) * 2]           = nc[t][0];
            sN[rr * 4 + (lane & 3) * 2 + 1]       = nc[t][1];
            sN[(rr + 8) * 4 + (lane & 3) * 2]     = nc[t][2];
            sN[(rr + 8) * 4 + (lane & 3) * 2 + 1] = nc[t][3];
        }
    }
}

// main 128x128xK=128 MMA from sA x bank buffer -> acc
__device__ __forceinline__ void bank_mma(uint32_t sal, uint32_t sbB, int wm, int wn, int lane,
                                         float acc[2][8][4])
{
    #pragma unroll
    for (int ks = 0; ks < 8; ks++) {
        uint32_t ah[2][4], al[2][4];
        #pragma unroll
        for (int t = 0; t < 2; t++) {
            uint32_t aaddr = sal + CB_SAH + (ks >> 2) * 16384 +
                SW128((uint32_t)((wm * 32 + t * 16 + (lane & 15)) * 128 + (ks & 3) * 32 + (lane >> 4) * 16));
            ldsm4(ah[t], aaddr);
            ldsm4(al[t], aaddr + 32768);
        }
        #pragma unroll
        for (int nt = 0; nt < 4; nt++) {
            uint32_t baddr = sbB + (ks >> 2) * 16384 +
                SW128((uint32_t)((wn * 64 + nt * 16 + ((lane >> 4) << 3) + (lane & 7)) * 128 +
                                 (ks & 3) * 32 + ((lane >> 3) & 1) * 16));
            uint32_t bh[4], bl[4];
            ldsm4(bh, baddr);
            ldsm4(bl, baddr + 32768);
            #pragma unroll
            for (int t = 0; t < 2; t++) {
                mma_bf16(acc[t][nt * 2 + 0], ah[t], bh);
                mma_bf16(acc[t][nt * 2 + 0], ah[t], bl);
                mma_bf16(acc[t][nt * 2 + 0], al[t], bh);
                mma_bf16(acc[t][nt * 2 + 1], ah[t], bh + 2);
                mma_bf16(acc[t][nt * 2 + 1], ah[t], bl + 2);
                mma_bf16(acc[t][nt * 2 + 1], al[t], bh + 2);
            }
        }
    }
}

__device__ __forceinline__ void copy_bank(const __nv_bfloat16* mTh, const __nv_bfloat16* mTl,
                                          int n, int h, int buf, uint32_t sal, int tid)
{
    const __nv_bfloat16* sh = mTh + ((size_t)(n * NH + h) << 14);
    const __nv_bfloat16* sl = mTl + ((size_t)(n * NH + h) << 14);
    uint32_t dst = sal + CB_SB + buf * 65536;
    #pragma unroll
    for (int i = 0; i < 8; i++) {
        int id = tid + i * 256;
        cp_async16(dst + id * 16, sh + id * 8);
        cp_async16(dst + 32768 + id * 16, sl + id * 8);
    }
}

__global__ __launch_bounds__(256, 1) void combined_hmma(
    const float* __restrict__ q,
    const __nv_bfloat16* __restrict__ mTh, const __nv_bfloat16* __restrict__ mTl,
    const __nv_bfloat16* __restrict__ nTh, const __nv_bfloat16* __restrict__ nTl,
    float* __restrict__ comb)
{
    extern __shared__ char smem[];
    uint32_t sraw = smem_to_u32(smem);
    uint32_t sal = (sraw + 1023u) & ~1023u;
    char* sb = smem + (sal - sraw);
    int tid = threadIdx.x, lane = tid & 31, wid = tid >> 5;
    int wm = wid & 3, wn = wid >> 2;
    int h = blockIdx.y;
    int row0 = blockIdx.x * 128;

    // issue async copies: G0 = {norm tiles, bank0->buf0}, G1 = {bank1->buf1}
    copy_bank(mTh, mTl, 0, h, 0, sal, tid);
    if (tid < 128) {
        cp_async16(sal + CB_SNTH + tid * 16, nTh + h * 1024 + tid * 8);
        cp_async16(sal + CB_SNTL + tid * 16, nTl + h * 1024 + tid * 8);
    }
    cp_commit();
    copy_bank(mTh, mTl, 1, h, 1, sal, tid);
    cp_commit();

    // sigma(q) -> sA hi/lo
    sigma_to_smem(q, row0, h, sb, tid);
    __syncthreads();

    asm volatile("cp.async.wait_group 1;" ::: "memory");
    __syncthreads();
    if (wn == 0) norm_mma(sal, sb, wm, lane);
    __syncthreads();

    // coef = weff / max(norm, eps)
    float* sN = (float*)(sb + CB_SNORM);
    float* sC = (float*)(sb + CB_SCOEF);
    {
        int rr = tid >> 1, base = (tid & 1) * 2;
        sC[rr * 4 + base]     = g_weff[h][base]     / fmaxf(sN[rr * 4 + base], EPSF);
        sC[rr * 4 + base + 1] = g_weff[h][base + 1] / fmaxf(sN[rr * 4 + base + 1], EPSF);
    }
    __syncthreads();

    float fin[2][8][4];
    #pragma unroll
    for (int t = 0; t < 2; t++)
        #pragma unroll
        for (int j = 0; j < 8; j++)
            #pragma unroll
            for (int p = 0; p < 4; p++) fin[t][j][p] = 0.f;

    for (int n = 0; n < NBANK; n++) {
        if (n < 3) { asm volatile("cp.async.wait_group 1;" ::: "memory"); }
        else       { asm volatile("cp.async.wait_group 0;" ::: "memory"); }
        __syncthreads();
        float acc[2][8][4];
        #pragma unroll
        for (int t = 0; t < 2; t++)
            #pragma unroll
            for (int j = 0; j < 8; j++)
                #pragma unroll
                for (int p = 0; p < 4; p++) acc[t][j][p] = 0.f;
        bank_mma(sal, sal + CB_SB + (n & 1) * 65536, wm, wn, lane, acc);
        __syncthreads();
        if (n + 2 < NBANK) { copy_bank(mTh, mTl, n + 2, h, n & 1, sal, tid); cp_commit(); }
        #pragma unroll
        for (int t = 0; t < 2; t++) {
            int rrA = wm * 32 + t * 16 + (lane >> 2);
            float cA = sC[rrA * 4 + n], cB = sC[(rrA + 8) * 4 + n];
            #pragma unroll
            for (int j = 0; j < 8; j++) {
                fin[t][j][0] += cA * acc[t][j][0];
                fin[t][j][1] += cA * acc[t][j][1];
                fin[t][j][2] += cB * acc[t][j][2];
                fin[t][j][3] += cB * acc[t][j][3];
            }
        }
    }

    #pragma unroll
    for (int t = 0; t < 2; t++) {
        int rr = row0 + wm * 32 + t * 16 + (lane >> 2);
        #pragma unroll
        for (int j = 0; j < 8; j++) {
            int col = h * DD + wn * 64 + j * 8 + (lane & 3) * 2;
            *(float2*)&comb[(size_t)rr * HIDC + col]       = make_float2(fin[t][j][0], fin[t][j][1]);
            *(float2*)&comb[(size_t)(rr + 8) * HIDC + col] = make_float2(fin[t][j][2], fin[t][j][3]);
        }
    }
}

__global__ __launch_bounds__(256, 1) void deltav_hmma(
    const float* __restrict__ k, float* __restrict__ v,
    const __nv_bfloat16* __restrict__ mTh, const __nv_bfloat16* __restrict__ mTl,
    const __nv_bfloat16* __restrict__ nTh, const __nv_bfloat16* __restrict__ nTl,
    float* __restrict__ nsum)
{
    extern __shared__ char smem[];
    uint32_t sraw = smem_to_u32(smem);
    uint32_t sal = (sraw + 1023u) & ~1023u;
    char* sb = smem + (sal - sraw);
    int tid = threadIdx.x, lane = tid & 31, wid = tid >> 5;
    int wm = wid & 3, wn = wid >> 2;
    int h = blockIdx.y;
    int row0 = blockIdx.x * 128;

    copy_bank(mTh, mTl, 0, h, 0, sal, tid);   // bank 0 only
    if (tid < 128) {
        cp_async16(sal + CB_SNTH + tid * 16, nTh + h * 1024 + tid * 8);
        cp_async16(sal + CB_SNTL + tid * 16, nTl + h * 1024 + tid * 8);
    }
    cp_commit();

    sigma_to_smem(k, row0, h, sb, tid);
    __syncthreads();

    asm volatile("cp.async.wait_group 0;" ::: "memory");
    __syncthreads();
    if (wn == 0) norm_mma(sal, sb, wm, lane);

    // column sums of sigma_k (hi+lo) over this 128-row tile
    {
        int col = tid & 127, hf = tid >> 7;
        float s = 0.f;
        for (int r = hf * 64; r < hf * 64 + 64; r++) {
            uint32_t off = (uint32_t)((col >> 6) * 16384) + SW128((uint32_t)(r * 128 + (col & 63) * 2));
            s += __bfloat162float(*(__nv_bfloat16*)(sb + CB_SAH + off))
               + __bfloat162float(*(__nv_bfloat16*)(sb + CB_SAL + off));
        }
        ((float*)(sb + CB_SSUM))[hf * 128 + col] = s;
    }
    __syncthreads();

    float* sN = (float*)(sb + CB_SNORM);
    float* sC = (float*)(sb + CB_SCOEF);
    if (tid < 128) {
        sC[tid] = 1.f / fmaxf(sN[tid * 4], EPSF);   // bank 0 norm col
        float* ss = (float*)(sb + CB_SSUM);
        nsum[(size_t)(h * 128 + blockIdx.x) * DD + tid] = ss[tid] + ss[128 + tid];
    }
    __syncthreads();

    float acc[2][8][4];
    #pragma unroll
    for (int t = 0; t < 2; t++)
        #pragma unroll
        for (int j = 0; j < 8; j++)
            #pragma unroll
            for (int p = 0; p < 4; p++) acc[t][j][p] = 0.f;
    bank_mma(sal, sal + CB_SB, wm, wn, lane, acc);

    #pragma unroll
    for (int t = 0; t < 2; t++) {
        int rloc = wm * 32 + t * 16 + (lane >> 2);
        float invA = sC[rloc], invB = sC[rloc + 8];
        int rr = row0 + rloc;
        #pragma unroll
        for (int j = 0; j < 8; j++) {
            int col = h * DD + wn * 64 + j * 8 + (lane & 3) * 2;
            float2 v0 = *(float2*)&v[(size_t)rr * HIDC + col];
            float2 v1 = *(float2*)&v[(size_t)(rr + 8) * HIDC + col];
            v0.x -= acc[t][j][0] * invA; v0.y -= acc[t][j][1] * invA;
            v1.x -= acc[t][j][2] * invB; v1.y -= acc[t][j][3] * invB;
            *(float2*)&v[(size_t)rr * HIDC + col]       = v0;
            *(float2*)&v[(size_t)(rr + 8) * HIDC + col] = v1;
        }
    }
}

// ===================== K3b: mem_update split-K (FFMA) =====================
__global__ __launch_bounds__(256) void memu_kernel(
    const float* __restrict__ k, const float* __restrict__ dv,
    float* __restrict__ part)
{
    __shared__ float sk[16][DD + 4];
    __shared__ float sv[16][DD + 4];
    int h = blockIdx.y;
    int r0 = blockIdx.x * 256;
    int tid = threadIdx.x;
    int tx = tid & 15, ty = tid >> 4;

    float acc[8][8];
    #pragma unroll
    for (int i = 0; i < 8; i++)
        #pragma unroll
        for (int j = 0; j < 8; j++) acc[i][j] = 0.f;

    for (int rc = 0; rc < 16; rc++) {
        #pragma unroll
        for (int it = 0; it < 2; it++) {
            int id = tid + it * 256;
            int rr = id >> 5, c4 = id & 31;
            size_t off = (size_t)(r0 + rc * 16 + rr) * HIDC + h * DD + c4 * 4;
            float4 kv = *(const float4*)&k[off];
            sk[rr][c4*4+0] = sigf(kv.x); sk[rr][c4*4+1] = sigf(kv.y);
            sk[rr][c4*4+2] = sigf(kv.z); sk[rr][c4*4+3] = sigf(kv.w);
            float4 vv = *(const float4*)&dv[off];
            *(float4*)&sv[rr][c4 * 4] = vv;
        }
        __syncthreads();
        #pragma unroll
        for (int rr = 0; rr < 16; rr++) {
            float4 a0 = *(float4*)&sk[rr][ty * 8];
            float4 a1 = *(float4*)&sk[rr][ty * 8 + 4];
            float a[8] = {a0.x,a0.y,a0.z,a0.w,a1.x,a1.y,a1.z,a1.w};
            float4 b0 = *(float4*)&sv[rr][tx * 8];
            float4 b1 = *(float4*)&sv[rr][tx * 8 + 4];
            float b[8] = {b0.x,b0.y,b0.z,b0.w,b1.x,b1.y,b1.z,b1.w};
            #pragma unroll
            for (int i = 0; i < 8; i++)
                #pragma unroll
                for (int j = 0; j < 8; j++)
                    acc[i][j] = fmaf(a[i], b[j], acc[i][j]);
        }
        __syncthreads();
    }
    size_t base = ((size_t)(h * 64 + blockIdx.x)) * DD * DD;
    #pragma unroll
    for (int i = 0; i < 8; i++) {
        size_t off = base + (size_t)(ty * 8 + i) * DD + tx * 8;
        float4 o0, o1;
        o0.x=acc[i][0]; o0.y=acc[i][1]; o0.z=acc[i][2]; o0.w=acc[i][3];
        o1.x=acc[i][4]; o1.y=acc[i][5]; o1.z=acc[i][6]; o1.w=acc[i][7];
        *(float4*)&part[off]     = o0;
        *(float4*)&part[off + 4] = o1;
    }
}

// ===================== K3c: reductions =====================
__global__ void reduce_mem_kernel(const float* __restrict__ part,
                                  const float* __restrict__ memories,
                                  float* __restrict__ out)
{
    int t = blockIdx.x * blockDim.x + threadIdx.x;
    int h = t >> 14;
    int rem = t & 16383;
    float s = 0.f;
    #pragma unroll 8
    for (int sl = 0; sl < 64; sl++)
        s += part[((size_t)(h * 64 + sl) << 14) + rem];
    out[OUT_MEM + t] = memories[(size_t)h * DD * DD + rem] + s * (1.f / (float)BQ);
}

__global__ void reduce_norm_kernel(const float* __restrict__ nsum,
                                   const float* __restrict__ mnorms,
                                   float* __restrict__ out)
{
    int t = blockIdx.x * blockDim.x + threadIdx.x;
    int h = t >> 7, d = t & 127;
    float s = 0.f;
    for (int b = 0; b < 128; b++)
        s += nsum[(size_t)(h * 128 + b) * DD + d];
    out[OUT_NORM + t] = mnorms[(size_t)h * DD + d] + s * 0.25f;
}

// ---------------------------------------------------------------------------
extern "C" void kernel_launch(void* const* d_in, const int* in_sizes, int n_in,
                              void* d_out, int out_size)
{
    const float* hs = (const float*)d_in[0];
    const float* Wq = (const float*)d_in[1];
    const float* Wk = (const float*)d_in[2];
    const float* Wv = (const float*)d_in[3];
    const float* Wo = (const float*)d_in[4];
    const float* bw = (const float*)d_in[5];
    const float* mem = (const float*)d_in[6];
    const float* mnm = (const float*)d_in[7];
    float* out = (float*)d_out;

    float *pq, *pk, *pv, *ppart, *pnsum;
    __nv_bfloat16 *hsh, *hsl, *wh, *wl, *cbh, *cbl, *mTh, *mTl, *nTh, *nTl;
    cudaGetSymbolAddress((void**)&pq, g_q);
    cudaGetSymbolAddress((void**)&pk, g_k);
    cudaGetSymbolAddress((void**)&pv, g_v);
    cudaGetSymbolAddress((void**)&ppart, g_part);
    cudaGetSymbolAddress((void**)&pnsum, g_nsum);
    cudaGetSymbolAddress((void**)&hsh, g_hs_hi);
    cudaGetSymbolAddress((void**)&hsl, g_hs_lo);
    cudaGetSymbolAddress((void**)&wh, g_w_hi);
    cudaGetSymbolAddress((void**)&wl, g_w_lo);
    cudaGetSymbolAddress((void**)&cbh, g_cb_hi);
    cudaGetSymbolAddress((void**)&cbl, g_cb_lo);
    cudaGetSymbolAddress((void**)&mTh, g_mTh);
    cudaGetSymbolAddress((void**)&mTl, g_mTl);
    cudaGetSymbolAddress((void**)&nTh, g_nTh);
    cudaGetSymbolAddress((void**)&nTl, g_nTl);

    static int smem_set = 0;
    if (!smem_set) {
        cudaFuncSetAttribute(hgemm_kernel, cudaFuncAttributeMaxDynamicSharedMemorySize, HG_SMEM);
        cudaFuncSetAttribute(combined_hmma, cudaFuncAttributeMaxDynamicSharedMemorySize, CB_SMEM);
        cudaFuncSetAttribute(deltav_hmma, cudaFuncAttributeMaxDynamicSharedMemorySize, CB_SMEM);
        smem_set = 1;
    }

    const size_t WSZ = (size_t)HIDC * HIDC;
    dim3 gg(HIDC / 128, BQ / 128);   // (16, 128)

    // launch order arranged so launch index 5 (ncu -s 5 -c 1) is hgemm_kernel
    prep_kernel<<<1, 128>>>(bw, mnm);                                         // 0
    cvt_split_kernel<<<(BQ * (size_t)HIDC) / 4 / 256, 256>>>(hs, hsh, hsl);   // 1
    cvt_split_kernel<<<WSZ / 4 / 256, 256>>>(Wq, wh + 0 * WSZ, wl + 0 * WSZ); // 2
    cvt_split_kernel<<<WSZ / 4 / 256, 256>>>(Wk, wh + 1 * WSZ, wl + 1 * WSZ); // 3
    cvt_split_kernel<<<WSZ / 4 / 256, 256>>>(Wv, wh + 2 * WSZ, wl + 2 * WSZ); // 4
    hgemm_kernel<<<gg, 256, HG_SMEM>>>(hsh, hsl, wh + 0 * WSZ, wl + 0 * WSZ, pq, HIDC); // 5 (profiled)
    cvt_split_kernel<<<WSZ / 4 / 256, 256>>>(Wo, wh + 3 * WSZ, wl + 3 * WSZ); // 6
    hgemm_kernel<<<gg, 256, HG_SMEM>>>(hsh, hsl, wh + 1 * WSZ, wl + 1 * WSZ, pk, HIDC);
    hgemm_kernel<<<gg, 256, HG_SMEM>>>(hsh, hsl, wh + 2 * WSZ, wl + 2 * WSZ, pv, HIDC);

    prep2_kernel<<<NBANK * NH, 256>>>(mem, mTh, mTl);
    normt_kernel<<<NH, 256>>>(mnm, nTh, nTl);

    combined_hmma<<<dim3(BQ / 128, NH), 256, CB_SMEM>>>(pq, mTh, mTl, nTh, nTl, pq);
    deltav_hmma<<<dim3(BQ / 128, NH), 256, CB_SMEM>>>(pk, pv, mTh, mTl, nTh, nTl, pnsum);
    memu_kernel<<<dim3(64, NH), 256>>>(pk, pv, ppart);

    reduce_mem_kernel<<<(NH * DD * DD) / 256, 256>>>(ppart, mem, out);
    reduce_norm_kernel<<<(NH * DD) / 256, 256>>>(pnsum, mnm, out);

    cvt_split_kernel<<<(BQ * (size_t)HIDC) / 4 / 256, 256>>>(pq, cbh, cbl);
    hgemm_kernel<<<gg, 256, HG_SMEM>>>(cbh, cbl, wh + 3 * WSZ, wl + 3 * WSZ, out, HIDC);
}

// round 9
// speedup vs baseline: 3.1565x; 1.0626x over previous
#include <cuda_runtime.h>
#include <cuda_bf16.h>
#include <math.h>
#include <stdint.h>

// Problem constants
#define BQ   16384          // B*S rows
#define HIDC 2048
#define NH   16
#define DD   128
#define NBANK 4
#define EPSF 1e-6f
#define GK   2048

#define OUT_MEM  ((size_t)BQ * HIDC)
#define OUT_NORM (OUT_MEM + (size_t)NH * DD * DD)

// -------- scratch (static device globals; no runtime allocation) ----------
__device__ float g_q[(size_t)BQ * HIDC];     // q proj
__device__ float g_k[(size_t)BQ * HIDC];     // k proj
__device__ float g_v[(size_t)BQ * HIDC];     // v proj, then delta_v (in place)
__device__ float g_part[(size_t)NH * 64 * DD * DD];
__device__ float g_nsum[(size_t)NH * 256 * DD];
__device__ float g_weff[NH][NBANK];

// bf16 hi/lo split buffers
__device__ __nv_bfloat16 g_hs_hi[(size_t)BQ * HIDC];
__device__ __nv_bfloat16 g_hs_lo[(size_t)BQ * HIDC];
__device__ __nv_bfloat16 g_w_hi[4][(size_t)HIDC * HIDC];   // Wq,Wk,Wv,Wo
__device__ __nv_bfloat16 g_w_lo[4][(size_t)HIDC * HIDC];
__device__ __nv_bfloat16 g_cb_hi[(size_t)BQ * HIDC];       // combined hi/lo
__device__ __nv_bfloat16 g_cb_lo[(size_t)BQ * HIDC];

// pre-swizzled transposed memories (B-operand layout) + norm tiles
__device__ __nv_bfloat16 g_mTh[(size_t)NBANK * NH * DD * DD];
__device__ __nv_bfloat16 g_mTl[(size_t)NBANK * NH * DD * DD];
__device__ __nv_bfloat16 g_nTh[(size_t)NH * 1024];
__device__ __nv_bfloat16 g_nTl[(size_t)NH * 1024];

__device__ __forceinline__ float sigf(float x) { return x > 0.f ? x + 1.f : expf(x); }

__device__ __forceinline__ uint32_t smem_to_u32(const void* p) {
    uint32_t a;
    asm("{ .reg .u64 t; cvta.to.shared.u64 t, %1; cvt.u32.u64 %0, t; }" : "=r"(a) : "l"(p));
    return a;
}
#define SW128(off) ((off) ^ (((off) >> 3) & 0x70))

__device__ __forceinline__ void cp_async16(uint32_t saddr, const void* gaddr) {
    asm volatile("cp.async.cg.shared.global [%0], [%1], 16;" :: "r"(saddr), "l"(gaddr));
}
__device__ __forceinline__ void cp_commit() {
    asm volatile("cp.async.commit_group;" ::: "memory");
}
__device__ __forceinline__ void ldsm4(uint32_t* r, uint32_t addr) {
    asm volatile("ldmatrix.sync.aligned.m8n8.x4.shared.b16 {%0,%1,%2,%3}, [%4];"
        : "=r"(r[0]), "=r"(r[1]), "=r"(r[2]), "=r"(r[3]) : "r"(addr));
}
__device__ __forceinline__ void ldsm2(uint32_t* r, uint32_t addr) {
    asm volatile("ldmatrix.sync.aligned.m8n8.x2.shared.b16 {%0,%1}, [%2];"
        : "=r"(r[0]), "=r"(r[1]) : "r"(addr));
}
__device__ __forceinline__ void mma_bf16(float* c, const uint32_t* a, const uint32_t* b) {
    asm volatile("mma.sync.aligned.m16n8k16.row.col.f32.bf16.bf16.f32 "
        "{%0,%1,%2,%3}, {%4,%5,%6,%7}, {%8,%9}, {%0,%1,%2,%3};"
        : "+f"(c[0]), "+f"(c[1]), "+f"(c[2]), "+f"(c[3])
        : "r"(a[0]), "r"(a[1]), "r"(a[2]), "r"(a[3]), "r"(b[0]), "r"(b[1]));
}

// ===================== fp32 -> bf16 hi/lo split =====================
__global__ void cvt_split_kernel(const float* __restrict__ x,
                                 __nv_bfloat16* __restrict__ hi,
                                 __nv_bfloat16* __restrict__ lo)
{
    size_t i = ((size_t)blockIdx.x * blockDim.x + threadIdx.x) * 4;
    float4 v = *(const float4*)(x + i);
    __nv_bfloat16 h0 = __float2bfloat16(v.x), h1 = __float2bfloat16(v.y);
    __nv_bfloat16 h2 = __float2bfloat16(v.z), h3 = __float2bfloat16(v.w);
    __nv_bfloat16 l0 = __float2bfloat16(v.x - __bfloat162float(h0));
    __nv_bfloat16 l1 = __float2bfloat16(v.y - __bfloat162float(h1));
    __nv_bfloat16 l2 = __float2bfloat16(v.z - __bfloat162float(h2));
    __nv_bfloat16 l3 = __float2bfloat16(v.w - __bfloat162float(h3));
    __nv_bfloat162* ph = (__nv_bfloat162*)(hi + i);
    __nv_bfloat162* pl = (__nv_bfloat162*)(lo + i);
    ph[0] = __nv_bfloat162(h0, h1); ph[1] = __nv_bfloat162(h2, h3);
    pl[0] = __nv_bfloat162(l0, l1); pl[1] = __nv_bfloat162(l2, l3);
}

// ===================== HMMA GEMM: C[M,N] = A[M,K] @ B[N,K]^T =====================
// bf16 hi/lo 3-pass. Block 128(m) x 256(n), warp tile 64x64, K-chunk 64, 2-stage.
#define SA_H 0
#define SA_L 16384
#define SB_H 32768
#define SB_L 65536
#define STG2 98304
#define NCHUNK 32           // K / 64
#define HG_SMEM (2 * STG2 + 1024)

__device__ __forceinline__ void load_stage(
    const __nv_bfloat16* __restrict__ Ah, const __nv_bfloat16* __restrict__ Al,
    const __nv_bfloat16* __restrict__ Bh, const __nv_bfloat16* __restrict__ Bl,
    uint32_t sb, int bm, int bn, int k0, int tid)
{
    #pragma unroll
    for (int it = 0; it < 4; it++) {
        int id = tid + it * 256;            // 0..1023 : A rows 0..127
        int r = id >> 3, c = id & 7;
        uint32_t sw = SW128((uint32_t)(r * 128 + c * 16));
        size_t ga = (size_t)(bm + r) * GK + k0 + c * 8;
        cp_async16(sb + SA_H + sw, Ah + ga);
        cp_async16(sb + SA_L + sw, Al + ga);
    }
    #pragma unroll
    for (int it = 0; it < 8; it++) {
        int id = tid + it * 256;            // 0..2047 : B rows 0..255
        int r = id >> 3, c = id & 7;
        uint32_t sw = SW128((uint32_t)(r * 128 + c * 16));
        size_t gb = (size_t)(bn + r) * GK + k0 + c * 8;
        cp_async16(sb + SB_H + sw, Bh + gb);
        cp_async16(sb + SB_L + sw, Bl + gb);
    }
}

__global__ __launch_bounds__(256, 1)
void hgemm_kernel(const __nv_bfloat16* __restrict__ Ah, const __nv_bfloat16* __restrict__ Al,
                  const __nv_bfloat16* __restrict__ Bh, const __nv_bfloat16* __restrict__ Bl,
                  float* __restrict__ C, int N)
{
    extern __shared__ char smem[];
    uint32_t sraw = smem_to_u32(smem);
    uint32_t sal = (sraw + 1023u) & ~1023u;

    int tid = threadIdx.x;
    int lane = tid & 31, wid = tid >> 5;
    int wm = wid >> 2, wn = wid & 3;        // warp tile 64(m) x 64(n), 2x4 warps
    int bm = blockIdx.y * 128;
    int bn = blockIdx.x * 256;

    float acc[4][8][4];
    #pragma unroll
    for (int t = 0; t < 4; t++)
        #pragma unroll
        for (int n = 0; n < 8; n++)
            #pragma unroll
            for (int j = 0; j < 4; j++) acc[t][n][j] = 0.f;

    load_stage(Ah, Al, Bh, Bl, sal, bm, bn, 0, tid);
    cp_commit();
    load_stage(Ah, Al, Bh, Bl, sal + STG2, bm, bn, 64, tid);
    cp_commit();

    // intra-warp ldmatrix base offsets
    uint32_t a_base = (uint32_t)((wm * 64 + (lane & 15)) * 128 + (lane >> 4) * 16);
    uint32_t b_base = (uint32_t)((wn * 64 + ((lane >> 4) << 3) + (lane & 7)) * 128 +
                                 ((lane >> 3) & 1) * 16);

    for (int c = 0; c < NCHUNK; c++) {
        if (c == NCHUNK - 1) { asm volatile("cp.async.wait_group 0;" ::: "memory"); }
        else                 { asm volatile("cp.async.wait_group 1;" ::: "memory"); }
        __syncthreads();
        uint32_t sb = sal + (c & 1) * STG2;

        #pragma unroll
        for (int ks = 0; ks < 4; ks++) {
            uint32_t ah[4][4], al[4][4];
            #pragma unroll
            for (int t = 0; t < 4; t++) {
                uint32_t aaddr = sb + SA_H + SW128(a_base + t * 16 * 128 + ks * 32);
                ldsm4(ah[t], aaddr);
                ldsm4(al[t], aaddr + (SA_L - SA_H));
            }
            #pragma unroll
            for (int ng = 0; ng < 4; ng++) {
                uint32_t baddr = sb + SB_H + SW128(b_base + ng * 16 * 128 + ks * 32);
                uint32_t bh[4], bl[4];
                ldsm4(bh, baddr);
                ldsm4(bl, baddr + (SB_L - SB_H));
                #pragma unroll
                for (int t = 0; t < 4; t++) {
                    mma_bf16(acc[t][ng * 2 + 0], ah[t], bh);
                    mma_bf16(acc[t][ng * 2 + 0], ah[t], bl);
                    mma_bf16(acc[t][ng * 2 + 0], al[t], bh);
                    mma_bf16(acc[t][ng * 2 + 1], ah[t], bh + 2);
                    mma_bf16(acc[t][ng * 2 + 1], ah[t], bl + 2);
                    mma_bf16(acc[t][ng * 2 + 1], al[t], bh + 2);
                }
            }
        }
        __syncthreads();
        if (c + 2 < NCHUNK) {
            load_stage(Ah, Al, Bh, Bl, sal + (c & 1) * STG2, bm, bn, (c + 2) * 64, tid);
            cp_commit();
        }
    }

    #pragma unroll
    for (int t = 0; t < 4; t++) {
        int r0 = bm + wm * 64 + t * 16 + (lane >> 2);
        #pragma unroll
        for (int nt = 0; nt < 8; nt++) {
            int col = bn + wn * 64 + nt * 8 + (lane & 3) * 2;
            *(float2*)&C[(size_t)r0 * N + col]       = make_float2(acc[t][nt][0], acc[t][nt][1]);
            *(float2*)&C[(size_t)(r0 + 8) * N + col] = make_float2(acc[t][nt][2], acc[t][nt][3]);
        }
    }
}

// ===================== K0: softmax of bank weights + active flags =====================
__global__ void prep_kernel(const float* __restrict__ bw, const float* __restrict__ mn) {
    __shared__ float bsum[NBANK];
    int tid = threadIdx.x;
    int w = tid >> 5, lane = tid & 31;
    if (w < NBANK) {
        float s = 0.f;
        for (int i = lane; i < NH * DD; i += 32) s += mn[w * NH * DD + i];
        #pragma unroll
        for (int o = 16; o; o >>= 1) s += __shfl_down_sync(0xffffffffu, s, o);
        if (lane == 0) bsum[w] = s;
    }
    __syncthreads();
    if (tid < NH) {
        float x0 = bw[tid * 4 + 0], x1 = bw[tid * 4 + 1];
        float x2 = bw[tid * 4 + 2], x3 = bw[tid * 4 + 3];
        float m = fmaxf(fmaxf(x0, x1), fmaxf(x2, x3));
        float e0 = expf(x0 - m), e1 = expf(x1 - m), e2 = expf(x2 - m), e3 = expf(x3 - m);
        float inv = 1.f / (e0 + e1 + e2 + e3);
        g_weff[tid][0] = e0 * inv * (bsum[0] >= EPSF ? 1.f : 0.f);
        g_weff[tid][1] = e1 * inv * (bsum[1] >= EPSF ? 1.f : 0.f);
        g_weff[tid][2] = e2 * inv * (bsum[2] >= EPSF ? 1.f : 0.f);
        g_weff[tid][3] = e3 * inv * (bsum[3] >= EPSF ? 1.f : 0.f);
    }
}

// ===================== prep2: memories -> transposed, split, pre-swizzled =====================
__global__ void prep2_kernel(const float* __restrict__ mem,
                             __nv_bfloat16* __restrict__ mTh, __nv_bfloat16* __restrict__ mTl)
{
    int nh = blockIdx.x;     // 0..63
    const float* src = mem + (size_t)nh * 16384;
    __nv_bfloat16* dh = mTh + (size_t)nh * 16384;
    __nv_bfloat16* dl = mTl + (size_t)nh * 16384;
    for (int i = threadIdx.x; i < 16384; i += 256) {
        int d = i >> 7, e = i & 127;
        float v = src[d * 128 + e];
        __nv_bfloat16 hi = __float2bfloat16(v);
        __nv_bfloat16 lo = __float2bfloat16(v - __bfloat162float(hi));
        uint32_t off = ((uint32_t)(d >> 6) << 13) +
                       (SW128((uint32_t)(e * 128 + (d & 63) * 2)) >> 1);
        dh[off] = hi; dl[off] = lo;
    }
}

__global__ void normt_kernel(const float* __restrict__ mnm,
                             __nv_bfloat16* __restrict__ nTh, __nv_bfloat16* __restrict__ nTl)
{
    int h = blockIdx.x;
    for (int i = threadIdx.x; i < 1024; i += 256) {
        int nr = i >> 7, d = i & 127;
        float v = (nr < NBANK) ? mnm[(size_t)(nr * NH + h) * DD + d] : 0.f;
        __nv_bfloat16 hi = __float2bfloat16(v);
        __nv_bfloat16 lo = __float2bfloat16(v - __bfloat162float(hi));
        uint32_t off = ((uint32_t)(d >> 6) << 9) +
                       (SW128((uint32_t)(nr * 128 + (d & 63) * 2)) >> 1);
        nTh[h * 1024 + off] = hi; nTl[h * 1024 + off] = lo;
    }
}

// ===================== HMMA combined / deltav =====================
#define CB_SAH   0
#define CB_SAL   32768
#define CB_SB    65536
#define CB_SNTH  196608
#define CB_SNTL  198656
#define CB_SNORM 200704
#define CB_SCOEF 202752
#define CB_SSUM  204800
#define CB_SMEM  207872

__device__ __forceinline__ void sigma_to_smem(const float* __restrict__ src, int row0, int h,
                                              char* sb, int tid)
{
    #pragma unroll
    for (int i = 0; i < 16; i++) {
        int id = tid + i * 256;
        int r = id >> 5, c4 = id & 31;
        float4 v = *(const float4*)&src[(size_t)(row0 + r) * HIDC + h * DD + c4 * 4];
        float s0 = sigf(v.x), s1 = sigf(v.y), s2 = sigf(v.z), s3 = sigf(v.w);
        __nv_bfloat16 h0 = __float2bfloat16(s0), h1 = __float2bfloat16(s1);
        __nv_bfloat16 h2 = __float2bfloat16(s2), h3 = __float2bfloat16(s3);
        __nv_bfloat16 l0 = __float2bfloat16(s0 - __bfloat162float(h0));
        __nv_bfloat16 l1 = __float2bfloat16(s1 - __bfloat162float(h1));
        __nv_bfloat16 l2 = __float2bfloat16(s2 - __bfloat162float(h2));
        __nv_bfloat16 l3 = __float2bfloat16(s3 - __bfloat162float(h3));
        int d0 = c4 * 4;
        uint32_t off = (uint32_t)((d0 >> 6) * 16384) + SW128((uint32_t)(r * 128 + (d0 & 63) * 2));
        *(__nv_bfloat162*)(sb + CB_SAH + off)     = __nv_bfloat162(h0, h1);
        *(__nv_bfloat162*)(sb + CB_SAH + off + 4) = __nv_bfloat162(h2, h3);
        *(__nv_bfloat162*)(sb + CB_SAL + off)     = __nv_bfloat162(l0, l1);
        *(__nv_bfloat162*)(sb + CB_SAL + off + 4) = __nv_bfloat162(l2, l3);
    }
}

__device__ __forceinline__ void norm_mma(uint32_t sal, char* sb, int wm, int lane)
{
    float nc[2][4];
    #pragma unroll
    for (int t = 0; t < 2; t++)
        #pragma unroll
        for (int j = 0; j < 4; j++) nc[t][j] = 0.f;
    #pragma unroll
    for (int ks = 0; ks < 8; ks++) {
        uint32_t ah[2][4], al[2][4];
        #pragma unroll
        for (int t = 0; t < 2; t++) {
            uint32_t aaddr = sal + CB_SAH + (ks >> 2) * 16384 +
                SW128((uint32_t)((wm * 32 + t * 16 + (lane & 15)) * 128 + (ks & 3) * 32 + (lane >> 4) * 16));
            ldsm4(ah[t], aaddr);
            ldsm4(al[t], aaddr + 32768);
        }
        uint32_t bh[2], bl[2];
        uint32_t naddr = sal + CB_SNTH + (ks >> 2) * 1024 +
            SW128((uint32_t)((lane & 7) * 128 + (ks & 3) * 32 + ((lane >> 3) & 1) * 16));
        ldsm2(bh, naddr);
        ldsm2(bl, naddr + 2048);
        #pragma unroll
        for (int t = 0; t < 2; t++) {
            mma_bf16(nc[t], ah[t], bh);
            mma_bf16(nc[t], al[t], bh);
            mma_bf16(nc[t], ah[t], bl);
        }
    }
    float* sN = (float*)(sb + CB_SNORM);
    if ((lane & 3) < 2) {
        #pragma unroll
        for (int t = 0; t < 2; t++) {
            int rr = wm * 32 + t * 16 + (lane >> 2);
            sN[rr * 4 + (lane & 3) * 2]           = nc[t][0];
            sN[rr * 4 + (lane & 3) * 2 + 1]       = nc[t][1];
            sN[(rr + 8) * 4 + (lane & 3) * 2]     = nc[t][2];
            sN[(rr + 8) * 4 + (lane & 3) * 2 + 1] = nc[t][3];
        }
    }
}

__device__ __forceinline__ void bank_mma(uint32_t sal, uint32_t sbB, int wm, int wn, int lane,
                                         float acc[2][8][4])
{
    #pragma unroll
    for (int ks = 0; ks < 8; ks++) {
        uint32_t ah[2][4], al[2][4];
        #pragma unroll
        for (int t = 0; t < 2; t++) {
            uint32_t aaddr = sal + CB_SAH + (ks >> 2) * 16384 +
                SW128((uint32_t)((wm * 32 + t * 16 + (lane & 15)) * 128 + (ks & 3) * 32 + (lane >> 4) * 16));
            ldsm4(ah[t], aaddr);
            ldsm4(al[t], aaddr + 32768);
        }
        #pragma unroll
        for (int nt = 0; nt < 4; nt++) {
            uint32_t baddr = sbB + (ks >> 2) * 16384 +
                SW128((uint32_t)((wn * 64 + nt * 16 + ((lane >> 4) << 3) + (lane & 7)) * 128 +
                                 (ks & 3) * 32 + ((lane >> 3) & 1) * 16));
            uint32_t bh[4], bl[4];
            ldsm4(bh, baddr);
            ldsm4(bl, baddr + 32768);
            #pragma unroll
            for (int t = 0; t < 2; t++) {
                mma_bf16(acc[t][nt * 2 + 0], ah[t], bh);
                mma_bf16(acc[t][nt * 2 + 0], ah[t], bl);
                mma_bf16(acc[t][nt * 2 + 0], al[t], bh);
                mma_bf16(acc[t][nt * 2 + 1], ah[t], bh + 2);
                mma_bf16(acc[t][nt * 2 + 1], ah[t], bl + 2);
                mma_bf16(acc[t][nt * 2 + 1], al[t], bh + 2);
            }
        }
    }
}

__device__ __forceinline__ void copy_bank(const __nv_bfloat16* mTh, const __nv_bfloat16* mTl,
                                          int n, int h, int buf, uint32_t sal, int tid)
{
    const __nv_bfloat16* sh = mTh + ((size_t)(n * NH + h) << 14);
    const __nv_bfloat16* sl = mTl + ((size_t)(n * NH + h) << 14);
    uint32_t dst = sal + CB_SB + buf * 65536;
    #pragma unroll
    for (int i = 0; i < 8; i++) {
        int id = tid + i * 256;
        cp_async16(dst + id * 16, sh + id * 8);
        cp_async16(dst + 32768 + id * 16, sl + id * 8);
    }
}

__global__ __launch_bounds__(256, 1) void combined_hmma(
    const float* __restrict__ q,
    const __nv_bfloat16* __restrict__ mTh, const __nv_bfloat16* __restrict__ mTl,
    const __nv_bfloat16* __restrict__ nTh, const __nv_bfloat16* __restrict__ nTl,
    __nv_bfloat16* __restrict__ cbh, __nv_bfloat16* __restrict__ cbl)
{
    extern __shared__ char smem[];
    uint32_t sraw = smem_to_u32(smem);
    uint32_t sal = (sraw + 1023u) & ~1023u;
    char* sb = smem + (sal - sraw);
    int tid = threadIdx.x, lane = tid & 31, wid = tid >> 5;
    int wm = wid & 3, wn = wid >> 2;
    int h = blockIdx.y;
    int row0 = blockIdx.x * 128;

    copy_bank(mTh, mTl, 0, h, 0, sal, tid);
    if (tid < 128) {
        cp_async16(sal + CB_SNTH + tid * 16, nTh + h * 1024 + tid * 8);
        cp_async16(sal + CB_SNTL + tid * 16, nTl + h * 1024 + tid * 8);
    }
    cp_commit();
    copy_bank(mTh, mTl, 1, h, 1, sal, tid);
    cp_commit();

    sigma_to_smem(q, row0, h, sb, tid);
    __syncthreads();

    asm volatile("cp.async.wait_group 1;" ::: "memory");
    __syncthreads();
    if (wn == 0) norm_mma(sal, sb, wm, lane);
    __syncthreads();

    float* sN = (float*)(sb + CB_SNORM);
    float* sC = (float*)(sb + CB_SCOEF);
    {
        int rr = tid >> 1, base = (tid & 1) * 2;
        sC[rr * 4 + base]     = g_weff[h][base]     / fmaxf(sN[rr * 4 + base], EPSF);
        sC[rr * 4 + base + 1] = g_weff[h][base + 1] / fmaxf(sN[rr * 4 + base + 1], EPSF);
    }
    __syncthreads();

    float fin[2][8][4];
    #pragma unroll
    for (int t = 0; t < 2; t++)
        #pragma unroll
        for (int j = 0; j < 8; j++)
            #pragma unroll
            for (int p = 0; p < 4; p++) fin[t][j][p] = 0.f;

    for (int n = 0; n < NBANK; n++) {
        if (n < 3) { asm volatile("cp.async.wait_group 1;" ::: "memory"); }
        else       { asm volatile("cp.async.wait_group 0;" ::: "memory"); }
        __syncthreads();
        float acc[2][8][4];
        #pragma unroll
        for (int t = 0; t < 2; t++)
            #pragma unroll
            for (int j = 0; j < 8; j++)
                #pragma unroll
                for (int p = 0; p < 4; p++) acc[t][j][p] = 0.f;
        bank_mma(sal, sal + CB_SB + (n & 1) * 65536, wm, wn, lane, acc);
        __syncthreads();
        if (n + 2 < NBANK) { copy_bank(mTh, mTl, n + 2, h, n & 1, sal, tid); cp_commit(); }
        #pragma unroll
        for (int t = 0; t < 2; t++) {
            int rrA = wm * 32 + t * 16 + (lane >> 2);
            float cA = sC[rrA * 4 + n], cB = sC[(rrA + 8) * 4 + n];
            #pragma unroll
            for (int j = 0; j < 8; j++) {
                fin[t][j][0] += cA * acc[t][j][0];
                fin[t][j][1] += cA * acc[t][j][1];
                fin[t][j][2] += cB * acc[t][j][2];
                fin[t][j][3] += cB * acc[t][j][3];
            }
        }
    }

    // write combined directly as bf16 hi/lo (skip fp32 + separate cvt pass)
    #pragma unroll
    for (int t = 0; t < 2; t++) {
        int rr = row0 + wm * 32 + t * 16 + (lane >> 2);
        #pragma unroll
        for (int j = 0; j < 8; j++) {
            int col = h * DD + wn * 64 + j * 8 + (lane & 3) * 2;
            #pragma unroll
            for (int half = 0; half < 2; half++) {
                float f0 = fin[t][j][half * 2 + 0], f1 = fin[t][j][half * 2 + 1];
                __nv_bfloat16 h0 = __float2bfloat16(f0), h1 = __float2bfloat16(f1);
                __nv_bfloat16 l0 = __float2bfloat16(f0 - __bfloat162float(h0));
                __nv_bfloat16 l1 = __float2bfloat16(f1 - __bfloat162float(h1));
                size_t off = (size_t)(rr + half * 8) * HIDC + col;
                *(__nv_bfloat162*)(cbh + off) = __nv_bfloat162(h0, h1);
                *(__nv_bfloat162*)(cbl + off) = __nv_bfloat162(l0, l1);
            }
        }
    }
}

__global__ __launch_bounds__(256, 1) void deltav_hmma(
    const float* __restrict__ k, float* __restrict__ v,
    const __nv_bfloat16* __restrict__ mTh, const __nv_bfloat16* __restrict__ mTl,
    const __nv_bfloat16* __restrict__ nTh, const __nv_bfloat16* __restrict__ nTl,
    float* __restrict__ nsum)
{
    extern __shared__ char smem[];
    uint32_t sraw = smem_to_u32(smem);
    uint32_t sal = (sraw + 1023u) & ~1023u;
    char* sb = smem + (sal - sraw);
    int tid = threadIdx.x, lane = tid & 31, wid = tid >> 5;
    int wm = wid & 3, wn = wid >> 2;
    int h = blockIdx.y;
    int row0 = blockIdx.x * 128;

    copy_bank(mTh, mTl, 0, h, 0, sal, tid);
    if (tid < 128) {
        cp_async16(sal + CB_SNTH + tid * 16, nTh + h * 1024 + tid * 8);
        cp_async16(sal + CB_SNTL + tid * 16, nTl + h * 1024 + tid * 8);
    }
    cp_commit();

    sigma_to_smem(k, row0, h, sb, tid);
    __syncthreads();

    asm volatile("cp.async.wait_group 0;" ::: "memory");
    __syncthreads();
    if (wn == 0) norm_mma(sal, sb, wm, lane);

    {
        int col = tid & 127, hf = tid >> 7;
        float s = 0.f;
        for (int r = hf * 64; r < hf * 64 + 64; r++) {
            uint32_t off = (uint32_t)((col >> 6) * 16384) + SW128((uint32_t)(r * 128 + (col & 63) * 2));
            s += __bfloat162float(*(__nv_bfloat16*)(sb + CB_SAH + off))
               + __bfloat162float(*(__nv_bfloat16*)(sb + CB_SAL + off));
        }
        ((float*)(sb + CB_SSUM))[hf * 128 + col] = s;
    }
    __syncthreads();

    float* sN = (float*)(sb + CB_SNORM);
    float* sC = (float*)(sb + CB_SCOEF);
    if (tid < 128) {
        sC[tid] = 1.f / fmaxf(sN[tid * 4], EPSF);
        float* ss = (float*)(sb + CB_SSUM);
        nsum[(size_t)(h * 128 + blockIdx.x) * DD + tid] = ss[tid] + ss[128 + tid];
    }
    __syncthreads();

    float acc[2][8][4];
    #pragma unroll
    for (int t = 0; t < 2; t++)
        #pragma unroll
        for (int j = 0; j < 8; j++)
            #pragma unroll
            for (int p = 0; p < 4; p++) acc[t][j][p] = 0.f;
    bank_mma(sal, sal + CB_SB, wm, wn, lane, acc);

    #pragma unroll
    for (int t = 0; t < 2; t++) {
        int rloc = wm * 32 + t * 16 + (lane >> 2);
        float invA = sC[rloc], invB = sC[rloc + 8];
        int rr = row0 + rloc;
        #pragma unroll
        for (int j = 0; j < 8; j++) {
            int col = h * DD + wn * 64 + j * 8 + (lane & 3) * 2;
            float2 v0 = *(float2*)&v[(size_t)rr * HIDC + col];
            float2 v1 = *(float2*)&v[(size_t)(rr + 8) * HIDC + col];
            v0.x -= acc[t][j][0] * invA; v0.y -= acc[t][j][1] * invA;
            v1.x -= acc[t][j][2] * invB; v1.y -= acc[t][j][3] * invB;
            *(float2*)&v[(size_t)rr * HIDC + col]       = v0;
            *(float2*)&v[(size_t)(rr + 8) * HIDC + col] = v1;
        }
    }
}

// ===================== K3b: mem_update split-K (FFMA) =====================
__global__ __launch_bounds__(256) void memu_kernel(
    const float* __restrict__ k, const float* __restrict__ dv,
    float* __restrict__ part)
{
    __shared__ float sk[16][DD + 4];
    __shared__ float sv[16][DD + 4];
    int h = blockIdx.y;
    int r0 = blockIdx.x * 256;
    int tid = threadIdx.x;
    int tx = tid & 15, ty = tid >> 4;

    float acc[8][8];
    #pragma unroll
    for (int i = 0; i < 8; i++)
        #pragma unroll
        for (int j = 0; j < 8; j++) acc[i][j] = 0.f;

    for (int rc = 0; rc < 16; rc++) {
        #pragma unroll
        for (int it = 0; it < 2; it++) {
            int id = tid + it * 256;
            int rr = id >> 5, c4 = id & 31;
            size_t off = (size_t)(r0 + rc * 16 + rr) * HIDC + h * DD + c4 * 4;
            float4 kv = *(const float4*)&k[off];
            sk[rr][c4*4+0] = sigf(kv.x); sk[rr][c4*4+1] = sigf(kv.y);
            sk[rr][c4*4+2] = sigf(kv.z); sk[rr][c4*4+3] = sigf(kv.w);
            float4 vv = *(const float4*)&dv[off];
            *(float4*)&sv[rr][c4 * 4] = vv;
        }
        __syncthreads();
        #pragma unroll
        for (int rr = 0; rr < 16; rr++) {
            float4 a0 = *(float4*)&sk[rr][ty * 8];
            float4 a1 = *(float4*)&sk[rr][ty * 8 + 4];
            float a[8] = {a0.x,a0.y,a0.z,a0.w,a1.x,a1.y,a1.z,a1.w};
            float4 b0 = *(float4*)&sv[rr][tx * 8];
            float4 b1 = *(float4*)&sv[rr][tx * 8 + 4];
            float b[8] = {b0.x,b0.y,b0.z,b0.w,b1.x,b1.y,b1.z,b1.w};
            #pragma unroll
            for (int i = 0; i < 8; i++)
                #pragma unroll
                for (int j = 0; j < 8; j++)
                    acc[i][j] = fmaf(a[i], b[j], acc[i][j]);
        }
        __syncthreads();
    }
    size_t base = ((size_t)(h * 64 + blockIdx.x)) * DD * DD;
    #pragma unroll
    for (int i = 0; i < 8; i++) {
        size_t off = base + (size_t)(ty * 8 + i) * DD + tx * 8;
        float4 o0, o1;
        o0.x=acc[i][0]; o0.y=acc[i][1]; o0.z=acc[i][2]; o0.w=acc[i][3];
        o1.x=acc[i][4]; o1.y=acc[i][5]; o1.z=acc[i][6]; o1.w=acc[i][7];
        *(float4*)&part[off]     = o0;
        *(float4*)&part[off + 4] = o1;
    }
}

// ===================== K3c: reductions =====================
__global__ void reduce_mem_kernel(const float* __restrict__ part,
                                  const float* __restrict__ memories,
                                  float* __restrict__ out)
{
    int t = blockIdx.x * blockDim.x + threadIdx.x;
    int h = t >> 14;
    int rem = t & 16383;
    float s = 0.f;
    #pragma unroll 8
    for (int sl = 0; sl < 64; sl++)
        s += part[((size_t)(h * 64 + sl) << 14) + rem];
    out[OUT_MEM + t] = memories[(size_t)h * DD * DD + rem] + s * (1.f / (float)BQ);
}

__global__ void reduce_norm_kernel(const float* __restrict__ nsum,
                                   const float* __restrict__ mnorms,
                                   float* __restrict__ out)
{
    int t = blockIdx.x * blockDim.x + threadIdx.x;
    int h = t >> 7, d = t & 127;
    float s = 0.f;
    for (int b = 0; b < 128; b++)
        s += nsum[(size_t)(h * 128 + b) * DD + d];
    out[OUT_NORM + t] = mnorms[(size_t)h * DD + d] + s * 0.25f;
}

// ---------------------------------------------------------------------------
extern "C" void kernel_launch(void* const* d_in, const int* in_sizes, int n_in,
                              void* d_out, int out_size)
{
    const float* hs = (const float*)d_in[0];
    const float* Wq = (const float*)d_in[1];
    const float* Wk = (const float*)d_in[2];
    const float* Wv = (const float*)d_in[3];
    const float* Wo = (const float*)d_in[4];
    const float* bw = (const float*)d_in[5];
    const float* mem = (const float*)d_in[6];
    const float* mnm = (const float*)d_in[7];
    float* out = (float*)d_out;

    float *pq, *pk, *pv, *ppart, *pnsum;
    __nv_bfloat16 *hsh, *hsl, *wh, *wl, *cbh, *cbl, *mTh, *mTl, *nTh, *nTl;
    cudaGetSymbolAddress((void**)&pq, g_q);
    cudaGetSymbolAddress((void**)&pk, g_k);
    cudaGetSymbolAddress((void**)&pv, g_v);
    cudaGetSymbolAddress((void**)&ppart, g_part);
    cudaGetSymbolAddress((void**)&pnsum, g_nsum);
    cudaGetSymbolAddress((void**)&hsh, g_hs_hi);
    cudaGetSymbolAddress((void**)&hsl, g_hs_lo);
    cudaGetSymbolAddress((void**)&wh, g_w_hi);
    cudaGetSymbolAddress((void**)&wl, g_w_lo);
    cudaGetSymbolAddress((void**)&cbh, g_cb_hi);
    cudaGetSymbolAddress((void**)&cbl, g_cb_lo);
    cudaGetSymbolAddress((void**)&mTh, g_mTh);
    cudaGetSymbolAddress((void**)&mTl, g_mTl);
    cudaGetSymbolAddress((void**)&nTh, g_nTh);
    cudaGetSymbolAddress((void**)&nTl, g_nTl);

    static int smem_set = 0;
    if (!smem_set) {
        cudaFuncSetAttribute(hgemm_kernel, cudaFuncAttributeMaxDynamicSharedMemorySize, HG_SMEM);
        cudaFuncSetAttribute(combined_hmma, cudaFuncAttributeMaxDynamicSharedMemorySize, CB_SMEM);
        cudaFuncSetAttribute(deltav_hmma, cudaFuncAttributeMaxDynamicSharedMemorySize, CB_SMEM);
        smem_set = 1;
    }

    const size_t WSZ = (size_t)HIDC * HIDC;
    dim3 gg(HIDC / 256, BQ / 128);   // (8, 128)

    prep_kernel<<<1, 128>>>(bw, mnm);                                         // 0
    cvt_split_kernel<<<(BQ * (size_t)HIDC) / 4 / 256, 256>>>(hs, hsh, hsl);   // 1
    cvt_split_kernel<<<WSZ / 4 / 256, 256>>>(Wq, wh + 0 * WSZ, wl + 0 * WSZ); // 2
    cvt_split_kernel<<<WSZ / 4 / 256, 256>>>(Wk, wh + 1 * WSZ, wl + 1 * WSZ); // 3
    cvt_split_kernel<<<WSZ / 4 / 256, 256>>>(Wv, wh + 2 * WSZ, wl + 2 * WSZ); // 4
    hgemm_kernel<<<gg, 256, HG_SMEM>>>(hsh, hsl, wh + 0 * WSZ, wl + 0 * WSZ, pq, HIDC); // 5
    hgemm_kernel<<<gg, 256, HG_SMEM>>>(hsh, hsl, wh + 1 * WSZ, wl + 1 * WSZ, pk, HIDC); // 6
    cvt_split_kernel<<<WSZ / 4 / 256, 256>>>(Wo, wh + 3 * WSZ, wl + 3 * WSZ); // 7
    hgemm_kernel<<<gg, 256, HG_SMEM>>>(hsh, hsl, wh + 2 * WSZ, wl + 2 * WSZ, pv, HIDC); // 8

    prep2_kernel<<<NBANK * NH, 256>>>(mem, mTh, mTl);
    normt_kernel<<<NH, 256>>>(mnm, nTh, nTl);

    combined_hmma<<<dim3(BQ / 128, NH), 256, CB_SMEM>>>(pq, mTh, mTl, nTh, nTl, cbh, cbl);
    deltav_hmma<<<dim3(BQ / 128, NH), 256, CB_SMEM>>>(pk, pv, mTh, mTl, nTh, nTl, pnsum);
    memu_kernel<<<dim3(64, NH), 256>>>(pk, pv, ppart);

    reduce_mem_kernel<<<(NH * DD * DD) / 256, 256>>>(ppart, mem, out);
    reduce_norm_kernel<<<(NH * DD) / 256, 256>>>(pnsum, mnm, out);

    hgemm_kernel<<<gg, 256, HG_SMEM>>>(cbh, cbl, wh + 3 * WSZ, wl + 3 * WSZ, out, HIDC);
}

// round 12
// speedup vs baseline: 3.2983x; 1.0449x over previous
#include <cuda_runtime.h>
#include <cuda_bf16.h>
#include <math.h>
#include <stdint.h>

// Problem constants
#define BQ   16384          // B*S rows
#define HIDC 2048
#define NH   16
#define DD   128
#define NBANK 4
#define EPSF 1e-6f
#define GK   2048

#define OUT_MEM  ((size_t)BQ * HIDC)
#define OUT_NORM (OUT_MEM + (size_t)NH * DD * DD)

// -------- scratch (static device globals; no runtime allocation) ----------
__device__ float g_q[(size_t)BQ * HIDC];     // q proj
__device__ float g_k[(size_t)BQ * HIDC];     // k proj
__device__ float g_v[(size_t)BQ * HIDC];     // v proj
__device__ float g_part[(size_t)NH * 128 * DD * DD];  // per-rowblock mem-update partials
__device__ float g_nsum[(size_t)NH * 256 * DD];
__device__ float g_weff[NH][NBANK];

// bf16 hi/lo split buffers
__device__ __nv_bfloat16 g_hs_hi[(size_t)BQ * HIDC];
__device__ __nv_bfloat16 g_hs_lo[(size_t)BQ * HIDC];
__device__ __nv_bfloat16 g_w_hi[4][(size_t)HIDC * HIDC];   // Wq,Wk,Wv,Wo
__device__ __nv_bfloat16 g_w_lo[4][(size_t)HIDC * HIDC];
__device__ __nv_bfloat16 g_cb_hi[(size_t)BQ * HIDC];       // combined hi/lo
__device__ __nv_bfloat16 g_cb_lo[(size_t)BQ * HIDC];

// pre-swizzled transposed memories (B-operand layout) + norm tiles
__device__ __nv_bfloat16 g_mTh[(size_t)NBANK * NH * DD * DD];
__device__ __nv_bfloat16 g_mTl[(size_t)NBANK * NH * DD * DD];
__device__ __nv_bfloat16 g_nTh[(size_t)NH * 1024];
__device__ __nv_bfloat16 g_nTl[(size_t)NH * 1024];

__device__ __forceinline__ float sigf(float x) { return x > 0.f ? x + 1.f : expf(x); }

__device__ __forceinline__ uint32_t smem_to_u32(const void* p) {
    uint32_t a;
    asm("{ .reg .u64 t; cvta.to.shared.u64 t, %1; cvt.u32.u64 %0, t; }" : "=r"(a) : "l"(p));
    return a;
}
#define SW128(off) ((off) ^ (((off) >> 3) & 0x70))

__device__ __forceinline__ void cp_async16(uint32_t saddr, const void* gaddr) {
    asm volatile("cp.async.cg.shared.global [%0], [%1], 16;" :: "r"(saddr), "l"(gaddr));
}
__device__ __forceinline__ void cp_commit() {
    asm volatile("cp.async.commit_group;" ::: "memory");
}
__device__ __forceinline__ void ldsm4(uint32_t* r, uint32_t addr) {
    asm volatile("ldmatrix.sync.aligned.m8n8.x4.shared.b16 {%0,%1,%2,%3}, [%4];"
        : "=r"(r[0]), "=r"(r[1]), "=r"(r[2]), "=r"(r[3]) : "r"(addr));
}
__device__ __forceinline__ void ldsm4t(uint32_t* r, uint32_t addr) {
    asm volatile("ldmatrix.sync.aligned.m8n8.x4.trans.shared.b16 {%0,%1,%2,%3}, [%4];"
        : "=r"(r[0]), "=r"(r[1]), "=r"(r[2]), "=r"(r[3]) : "r"(addr));
}
__device__ __forceinline__ void ldsm2(uint32_t* r, uint32_t addr) {
    asm volatile("ldmatrix.sync.aligned.m8n8.x2.shared.b16 {%0,%1}, [%2];"
        : "=r"(r[0]), "=r"(r[1]) : "r"(addr));
}
__device__ __forceinline__ void mma_bf16(float* c, const uint32_t* a, const uint32_t* b) {
    asm volatile("mma.sync.aligned.m16n8k16.row.col.f32.bf16.bf16.f32 "
        "{%0,%1,%2,%3}, {%4,%5,%6,%7}, {%8,%9}, {%0,%1,%2,%3};"
        : "+f"(c[0]), "+f"(c[1]), "+f"(c[2]), "+f"(c[3])
        : "r"(a[0]), "r"(a[1]), "r"(a[2]), "r"(a[3]), "r"(b[0]), "r"(b[1]));
}

// ===================== fp32 -> bf16 hi/lo split =====================
__global__ void cvt_split_kernel(const float* __restrict__ x,
                                 __nv_bfloat16* __restrict__ hi,
                                 __nv_bfloat16* __restrict__ lo)
{
    size_t i = ((size_t)blockIdx.x * blockDim.x + threadIdx.x) * 4;
    float4 v = *(const float4*)(x + i);
    __nv_bfloat16 h0 = __float2bfloat16(v.x), h1 = __float2bfloat16(v.y);
    __nv_bfloat16 h2 = __float2bfloat16(v.z), h3 = __float2bfloat16(v.w);
    __nv_bfloat16 l0 = __float2bfloat16(v.x - __bfloat162float(h0));
    __nv_bfloat16 l1 = __float2bfloat16(v.y - __bfloat162float(h1));
    __nv_bfloat16 l2 = __float2bfloat16(v.z - __bfloat162float(h2));
    __nv_bfloat16 l3 = __float2bfloat16(v.w - __bfloat162float(h3));
    __nv_bfloat162* ph = (__nv_bfloat162*)(hi + i);
    __nv_bfloat162* pl = (__nv_bfloat162*)(lo + i);
    ph[0] = __nv_bfloat162(h0, h1); ph[1] = __nv_bfloat162(h2, h3);
    pl[0] = __nv_bfloat162(l0, l1); pl[1] = __nv_bfloat162(l2, l3);
}

// ===================== HMMA GEMM: C[M,N] = A[M,K] @ B[N,K]^T =====================
// bf16 hi/lo 3-pass. Block 128(m) x 256(n), warp tile 64x64, K-chunk 64, 2-stage.
#define SA_H 0
#define SA_L 16384
#define SB_H 32768
#define SB_L 65536
#define STG2 98304
#define NCHUNK 32           // K / 64
#define HG_SMEM (2 * STG2 + 1024)

__device__ __forceinline__ void load_stage(
    const __nv_bfloat16* __restrict__ Ah, const __nv_bfloat16* __restrict__ Al,
    const __nv_bfloat16* __restrict__ Bh, const __nv_bfloat16* __restrict__ Bl,
    uint32_t sb, int bm, int bn, int k0, int tid)
{
    #pragma unroll
    for (int it = 0; it < 4; it++) {
        int id = tid + it * 256;            // 0..1023 : A rows 0..127
        int r = id >> 3, c = id & 7;
        uint32_t sw = SW128((uint32_t)(r * 128 + c * 16));
        size_t ga = (size_t)(bm + r) * GK + k0 + c * 8;
        cp_async16(sb + SA_H + sw, Ah + ga);
        cp_async16(sb + SA_L + sw, Al + ga);
    }
    #pragma unroll
    for (int it = 0; it < 8; it++) {
        int id = tid + it * 256;            // 0..2047 : B rows 0..255
        int r = id >> 3, c = id & 7;
        uint32_t sw = SW128((uint32_t)(r * 128 + c * 16));
        size_t gb = (size_t)(bn + r) * GK + k0 + c * 8;
        cp_async16(sb + SB_H + sw, Bh + gb);
        cp_async16(sb + SB_L + sw, Bl + gb);
    }
}

__global__ __launch_bounds__(256, 1)
void hgemm_kernel(const __nv_bfloat16* __restrict__ Ah, const __nv_bfloat16* __restrict__ Al,
                  const __nv_bfloat16* __restrict__ Bh, const __nv_bfloat16* __restrict__ Bl,
                  float* __restrict__ C, int N)
{
    extern __shared__ char smem[];
    uint32_t sraw = smem_to_u32(smem);
    uint32_t sal = (sraw + 1023u) & ~1023u;

    int tid = threadIdx.x;
    int lane = tid & 31, wid = tid >> 5;
    int wm = wid >> 2, wn = wid & 3;        // warp tile 64(m) x 64(n), 2x4 warps
    int bm = blockIdx.y * 128;
    int bn = blockIdx.x * 256;

    float acc[4][8][4];
    #pragma unroll
    for (int t = 0; t < 4; t++)
        #pragma unroll
        for (int n = 0; n < 8; n++)
            #pragma unroll
            for (int j = 0; j < 4; j++) acc[t][n][j] = 0.f;

    load_stage(Ah, Al, Bh, Bl, sal, bm, bn, 0, tid);
    cp_commit();
    load_stage(Ah, Al, Bh, Bl, sal + STG2, bm, bn, 64, tid);
    cp_commit();

    uint32_t a_base = (uint32_t)((wm * 64 + (lane & 15)) * 128 + (lane >> 4) * 16);
    uint32_t b_base = (uint32_t)((wn * 64 + ((lane >> 4) << 3) + (lane & 7)) * 128 +
                                 ((lane >> 3) & 1) * 16);

    for (int c = 0; c < NCHUNK; c++) {
        if (c == NCHUNK - 1) { asm volatile("cp.async.wait_group 0;" ::: "memory"); }
        else                 { asm volatile("cp.async.wait_group 1;" ::: "memory"); }
        __syncthreads();
        uint32_t sb = sal + (c & 1) * STG2;

        #pragma unroll
        for (int ks = 0; ks < 4; ks++) {
            uint32_t ah[4][4], al[4][4];
            #pragma unroll
            for (int t = 0; t < 4; t++) {
                uint32_t aaddr = sb + SA_H + SW128(a_base + t * 16 * 128 + ks * 32);
                ldsm4(ah[t], aaddr);
                ldsm4(al[t], aaddr + (SA_L - SA_H));
            }
            #pragma unroll
            for (int ng = 0; ng < 4; ng++) {
                uint32_t baddr = sb + SB_H + SW128(b_base + ng * 16 * 128 + ks * 32);
                uint32_t bh[4], bl[4];
                ldsm4(bh, baddr);
                ldsm4(bl, baddr + (SB_L - SB_H));
                #pragma unroll
                for (int t = 0; t < 4; t++) {
                    mma_bf16(acc[t][ng * 2 + 0], ah[t], bh);
                    mma_bf16(acc[t][ng * 2 + 0], ah[t], bl);
                    mma_bf16(acc[t][ng * 2 + 0], al[t], bh);
                    mma_bf16(acc[t][ng * 2 + 1], ah[t], bh + 2);
                    mma_bf16(acc[t][ng * 2 + 1], ah[t], bl + 2);
                    mma_bf16(acc[t][ng * 2 + 1], al[t], bh + 2);
                }
            }
        }
        __syncthreads();
        if (c + 2 < NCHUNK) {
            load_stage(Ah, Al, Bh, Bl, sal + (c & 1) * STG2, bm, bn, (c + 2) * 64, tid);
            cp_commit();
        }
    }

    #pragma unroll
    for (int t = 0; t < 4; t++) {
        int r0 = bm + wm * 64 + t * 16 + (lane >> 2);
        #pragma unroll
        for (int nt = 0; nt < 8; nt++) {
            int col = bn + wn * 64 + nt * 8 + (lane & 3) * 2;
            *(float2*)&C[(size_t)r0 * N + col]       = make_float2(acc[t][nt][0], acc[t][nt][1]);
            *(float2*)&C[(size_t)(r0 + 8) * N + col] = make_float2(acc[t][nt][2], acc[t][nt][3]);
        }
    }
}

// ===================== K0: softmax of bank weights + active flags =====================
__global__ void prep_kernel(const float* __restrict__ bw, const float* __restrict__ mn) {
    __shared__ float bsum[NBANK];
    int tid = threadIdx.x;
    int w = tid >> 5, lane = tid & 31;
    if (w < NBANK) {
        float s = 0.f;
        for (int i = lane; i < NH * DD; i += 32) s += mn[w * NH * DD + i];
        #pragma unroll
        for (int o = 16; o; o >>= 1) s += __shfl_down_sync(0xffffffffu, s, o);
        if (lane == 0) bsum[w] = s;
    }
    __syncthreads();
    if (tid < NH) {
        float x0 = bw[tid * 4 + 0], x1 = bw[tid * 4 + 1];
        float x2 = bw[tid * 4 + 2], x3 = bw[tid * 4 + 3];
        float m = fmaxf(fmaxf(x0, x1), fmaxf(x2, x3));
        float e0 = expf(x0 - m), e1 = expf(x1 - m), e2 = expf(x2 - m), e3 = expf(x3 - m);
        float inv = 1.f / (e0 + e1 + e2 + e3);
        g_weff[tid][0] = e0 * inv * (bsum[0] >= EPSF ? 1.f : 0.f);
        g_weff[tid][1] = e1 * inv * (bsum[1] >= EPSF ? 1.f : 0.f);
        g_weff[tid][2] = e2 * inv * (bsum[2] >= EPSF ? 1.f : 0.f);
        g_weff[tid][3] = e3 * inv * (bsum[3] >= EPSF ? 1.f : 0.f);
    }
}

// ===================== prep2: memories -> transposed, split, pre-swizzled =====================
__global__ void prep2_kernel(const float* __restrict__ mem,
                             __nv_bfloat16* __restrict__ mTh, __nv_bfloat16* __restrict__ mTl)
{
    int nh = blockIdx.x;     // 0..63
    const float* src = mem + (size_t)nh * 16384;
    __nv_bfloat16* dh = mTh + (size_t)nh * 16384;
    __nv_bfloat16* dl = mTl + (size_t)nh * 16384;
    for (int i = threadIdx.x; i < 16384; i += 256) {
        int d = i >> 7, e = i & 127;
        float v = src[d * 128 + e];
        __nv_bfloat16 hi = __float2bfloat16(v);
        __nv_bfloat16 lo = __float2bfloat16(v - __bfloat162float(hi));
        uint32_t off = ((uint32_t)(d >> 6) << 13) +
                       (SW128((uint32_t)(e * 128 + (d & 63) * 2)) >> 1);
        dh[off] = hi; dl[off] = lo;
    }
}

__global__ void normt_kernel(const float* __restrict__ mnm,
                             __nv_bfloat16* __restrict__ nTh, __nv_bfloat16* __restrict__ nTl)
{
    int h = blockIdx.x;
    for (int i = threadIdx.x; i < 1024; i += 256) {
        int nr = i >> 7, d = i & 127;
        float v = (nr < NBANK) ? mnm[(size_t)(nr * NH + h) * DD + d] : 0.f;
        __nv_bfloat16 hi = __float2bfloat16(v);
        __nv_bfloat16 lo = __float2bfloat16(v - __bfloat162float(hi));
        uint32_t off = ((uint32_t)(d >> 6) << 9) +
                       (SW128((uint32_t)(nr * 128 + (d & 63) * 2)) >> 1);
        nTh[h * 1024 + off] = hi; nTl[h * 1024 + off] = lo;
    }
}

// ===================== HMMA combined / deltav =====================
#define CB_SAH   0
#define CB_SAL   32768
#define CB_SB    65536
#define CB_SNTH  196608
#define CB_SNTL  198656
#define CB_SNORM 200704
#define CB_SCOEF 202752
#define CB_SSUM  204800
#define CB_SMEM  207872

__device__ __forceinline__ void sigma_to_smem(const float* __restrict__ src, int row0, int h,
                                              char* sb, int tid)
{
    #pragma unroll
    for (int i = 0; i < 16; i++) {
        int id = tid + i * 256;
        int r = id >> 5, c4 = id & 31;
        float4 v = *(const float4*)&src[(size_t)(row0 + r) * HIDC + h * DD + c4 * 4];
        float s0 = sigf(v.x), s1 = sigf(v.y), s2 = sigf(v.z), s3 = sigf(v.w);
        __nv_bfloat16 h0 = __float2bfloat16(s0), h1 = __float2bfloat16(s1);
        __nv_bfloat16 h2 = __float2bfloat16(s2), h3 = __float2bfloat16(s3);
        __nv_bfloat16 l0 = __float2bfloat16(s0 - __bfloat162float(h0));
        __nv_bfloat16 l1 = __float2bfloat16(s1 - __bfloat162float(h1));
        __nv_bfloat16 l2 = __float2bfloat16(s2 - __bfloat162float(h2));
        __nv_bfloat16 l3 = __float2bfloat16(s3 - __bfloat162float(h3));
        int d0 = c4 * 4;
        uint32_t off = (uint32_t)((d0 >> 6) * 16384) + SW128((uint32_t)(r * 128 + (d0 & 63) * 2));
        *(__nv_bfloat162*)(sb + CB_SAH + off)     = __nv_bfloat162(h0, h1);
        *(__nv_bfloat162*)(sb + CB_SAH + off + 4) = __nv_bfloat162(h2, h3);
        *(__nv_bfloat162*)(sb + CB_SAL + off)     = __nv_bfloat162(l0, l1);
        *(__nv_bfloat162*)(sb + CB_SAL + off + 4) = __nv_bfloat162(l2, l3);
    }
}

__device__ __forceinline__ void norm_mma(uint32_t sal, char* sb, int wm, int lane)
{
    float nc[2][4];
    #pragma unroll
    for (int t = 0; t < 2; t++)
        #pragma unroll
        for (int j = 0; j < 4; j++) nc[t][j] = 0.f;
    #pragma unroll
    for (int ks = 0; ks < 8; ks++) {
        uint32_t ah[2][4], al[2][4];
        #pragma unroll
        for (int t = 0; t < 2; t++) {
            uint32_t aaddr = sal + CB_SAH + (ks >> 2) * 16384 +
                SW128((uint32_t)((wm * 32 + t * 16 + (lane & 15)) * 128 + (ks & 3) * 32 + (lane >> 4) * 16));
            ldsm4(ah[t], aaddr);
            ldsm4(al[t], aaddr + 32768);
        }
        uint32_t bh[2], bl[2];
        uint32_t naddr = sal + CB_SNTH + (ks >> 2) * 1024 +
            SW128((uint32_t)((lane & 7) * 128 + (ks & 3) * 32 + ((lane >> 3) & 1) * 16));
        ldsm2(bh, naddr);
        ldsm2(bl, naddr + 2048);
        #pragma unroll
        for (int t = 0; t < 2; t++) {
            mma_bf16(nc[t], ah[t], bh);
            mma_bf16(nc[t], al[t], bh);
            mma_bf16(nc[t], ah[t], bl);
        }
    }
    float* sN = (float*)(sb + CB_SNORM);
    if ((lane & 3) < 2) {
        #pragma unroll
        for (int t = 0; t < 2; t++) {
            int rr = wm * 32 + t * 16 + (lane >> 2);
            sN[rr * 4 + (lane & 3) * 2]           = nc[t][0];
            sN[rr * 4 + (lane & 3) * 2 + 1]       = nc[t][1];
            sN[(rr + 8) * 4 + (lane & 3) * 2]     = nc[t][2];
            sN[(rr + 8) * 4 + (lane & 3) * 2 + 1] = nc[t][3];
        }
    }
}

__device__ __forceinline__ void bank_mma(uint32_t sal, uint32_t sbB, int wm, int wn, int lane,
                                         float acc[2][8][4])
{
    #pragma unroll
    for (int ks = 0; ks < 8; ks++) {
        uint32_t ah[2][4], al[2][4];
        #pragma unroll
        for (int t = 0; t < 2; t++) {
            uint32_t aaddr = sal + CB_SAH + (ks >> 2) * 16384 +
                SW128((uint32_t)((wm * 32 + t * 16 + (lane & 15)) * 128 + (ks & 3) * 32 + (lane >> 4) * 16));
            ldsm4(ah[t], aaddr);
            ldsm4(al[t], aaddr + 32768);
        }
        #pragma unroll
        for (int nt = 0; nt < 4; nt++) {
            uint32_t baddr = sbB + (ks >> 2) * 16384 +
                SW128((uint32_t)((wn * 64 + nt * 16 + ((lane >> 4) << 3) + (lane & 7)) * 128 +
                                 (ks & 3) * 32 + ((lane >> 3) & 1) * 16));
            uint32_t bh[4], bl[4];
            ldsm4(bh, baddr);
            ldsm4(bl, baddr + 32768);
            #pragma unroll
            for (int t = 0; t < 2; t++) {
                mma_bf16(acc[t][nt * 2 + 0], ah[t], bh);
                mma_bf16(acc[t][nt * 2 + 0], ah[t], bl);
                mma_bf16(acc[t][nt * 2 + 0], al[t], bh);
                mma_bf16(acc[t][nt * 2 + 1], ah[t], bh + 2);
                mma_bf16(acc[t][nt * 2 + 1], ah[t], bl + 2);
                mma_bf16(acc[t][nt * 2 + 1], al[t], bh + 2);
            }
        }
    }
}

__device__ __forceinline__ void copy_bank(const __nv_bfloat16* mTh, const __nv_bfloat16* mTl,
                                          int n, int h, int buf, uint32_t sal, int tid)
{
    const __nv_bfloat16* sh = mTh + ((size_t)(n * NH + h) << 14);
    const __nv_bfloat16* sl = mTl + ((size_t)(n * NH + h) << 14);
    uint32_t dst = sal + CB_SB + buf * 65536;
    #pragma unroll
    for (int i = 0; i < 8; i++) {
        int id = tid + i * 256;
        cp_async16(dst + id * 16, sh + id * 8);
        cp_async16(dst + 32768 + id * 16, sl + id * 8);
    }
}

__global__ __launch_bounds__(256, 1) void combined_hmma(
    const float* __restrict__ q,
    const __nv_bfloat16* __restrict__ mTh, const __nv_bfloat16* __restrict__ mTl,
    const __nv_bfloat16* __restrict__ nTh, const __nv_bfloat16* __restrict__ nTl,
    __nv_bfloat16* __restrict__ cbh, __nv_bfloat16* __restrict__ cbl)
{
    extern __shared__ char smem[];
    uint32_t sraw = smem_to_u32(smem);
    uint32_t sal = (sraw + 1023u) & ~1023u;
    char* sb = smem + (sal - sraw);
    int tid = threadIdx.x, lane = tid & 31, wid = tid >> 5;
    int wm = wid & 3, wn = wid >> 2;
    int h = blockIdx.y;
    int row0 = blockIdx.x * 128;

    copy_bank(mTh, mTl, 0, h, 0, sal, tid);
    if (tid < 128) {
        cp_async16(sal + CB_SNTH + tid * 16, nTh + h * 1024 + tid * 8);
        cp_async16(sal + CB_SNTL + tid * 16, nTl + h * 1024 + tid * 8);
    }
    cp_commit();
    copy_bank(mTh, mTl, 1, h, 1, sal, tid);
    cp_commit();

    sigma_to_smem(q, row0, h, sb, tid);
    __syncthreads();

    asm volatile("cp.async.wait_group 1;" ::: "memory");
    __syncthreads();
    if (wn == 0) norm_mma(sal, sb, wm, lane);
    __syncthreads();

    float* sN = (float*)(sb + CB_SNORM);
    float* sC = (float*)(sb + CB_SCOEF);
    {
        int rr = tid >> 1, base = (tid & 1) * 2;
        sC[rr * 4 + base]     = g_weff[h][base]     / fmaxf(sN[rr * 4 + base], EPSF);
        sC[rr * 4 + base + 1] = g_weff[h][base + 1] / fmaxf(sN[rr * 4 + base + 1], EPSF);
    }
    __syncthreads();

    float fin[2][8][4];
    #pragma unroll
    for (int t = 0; t < 2; t++)
        #pragma unroll
        for (int j = 0; j < 8; j++)
            #pragma unroll
            for (int p = 0; p < 4; p++) fin[t][j][p] = 0.f;

    for (int n = 0; n < NBANK; n++) {
        if (n < 3) { asm volatile("cp.async.wait_group 1;" ::: "memory"); }
        else       { asm volatile("cp.async.wait_group 0;" ::: "memory"); }
        __syncthreads();
        float acc[2][8][4];
        #pragma unroll
        for (int t = 0; t < 2; t++)
            #pragma unroll
            for (int j = 0; j < 8; j++)
                #pragma unroll
                for (int p = 0; p < 4; p++) acc[t][j][p] = 0.f;
        bank_mma(sal, sal + CB_SB + (n & 1) * 65536, wm, wn, lane, acc);
        __syncthreads();
        if (n + 2 < NBANK) { copy_bank(mTh, mTl, n + 2, h, n & 1, sal, tid); cp_commit(); }
        #pragma unroll
        for (int t = 0; t < 2; t++) {
            int rrA = wm * 32 + t * 16 + (lane >> 2);
            float cA = sC[rrA * 4 + n], cB = sC[(rrA + 8) * 4 + n];
            #pragma unroll
            for (int j = 0; j < 8; j++) {
                fin[t][j][0] += cA * acc[t][j][0];
                fin[t][j][1] += cA * acc[t][j][1];
                fin[t][j][2] += cB * acc[t][j][2];
                fin[t][j][3] += cB * acc[t][j][3];
            }
        }
    }

    // write combined directly as bf16 hi/lo
    #pragma unroll
    for (int t = 0; t < 2; t++) {
        int rr = row0 + wm * 32 + t * 16 + (lane >> 2);
        #pragma unroll
        for (int j = 0; j < 8; j++) {
            int col = h * DD + wn * 64 + j * 8 + (lane & 3) * 2;
            #pragma unroll
            for (int half = 0; half < 2; half++) {
                float f0 = fin[t][j][half * 2 + 0], f1 = fin[t][j][half * 2 + 1];
                __nv_bfloat16 h0 = __float2bfloat16(f0), h1 = __float2bfloat16(f1);
                __nv_bfloat16 l0 = __float2bfloat16(f0 - __bfloat162float(h0));
                __nv_bfloat16 l1 = __float2bfloat16(f1 - __bfloat162float(h1));
                size_t off = (size_t)(rr + half * 8) * HIDC + col;
                *(__nv_bfloat162*)(cbh + off) = __nv_bfloat162(h0, h1);
                *(__nv_bfloat162*)(cbl + off) = __nv_bfloat162(l0, l1);
            }
        }
    }
}

// deltav + fused mem-update partial:
//   dv = v - (sigma_k@mem0)/knorm (registers) -> smem bf16 hi/lo
//   P[d,e] = sum_{r in block} sk[r,d]*dv[r,e] via ldmatrix.trans HMMA -> g_part
__global__ __launch_bounds__(256, 1) void deltav_hmma(
    const float* __restrict__ k, const float* __restrict__ v,
    const __nv_bfloat16* __restrict__ mTh, const __nv_bfloat16* __restrict__ mTl,
    const __nv_bfloat16* __restrict__ nTh, const __nv_bfloat16* __restrict__ nTl,
    float* __restrict__ nsum, float* __restrict__ part)
{
    extern __shared__ char smem[];
    uint32_t sraw = smem_to_u32(smem);
    uint32_t sal = (sraw + 1023u) & ~1023u;
    char* sb = smem + (sal - sraw);
    int tid = threadIdx.x, lane = tid & 31, wid = tid >> 5;
    int wm = wid & 3, wn = wid >> 2;
    int h = blockIdx.y;
    int row0 = blockIdx.x * 128;

    copy_bank(mTh, mTl, 0, h, 0, sal, tid);
    if (tid < 128) {
        cp_async16(sal + CB_SNTH + tid * 16, nTh + h * 1024 + tid * 8);
        cp_async16(sal + CB_SNTL + tid * 16, nTl + h * 1024 + tid * 8);
    }
    cp_commit();

    sigma_to_smem(k, row0, h, sb, tid);
    __syncthreads();

    asm volatile("cp.async.wait_group 0;" ::: "memory");
    __syncthreads();
    if (wn == 0) norm_mma(sal, sb, wm, lane);

    {   // column sums of sigma_k (hi+lo) over this 128-row tile
        int col = tid & 127, hf = tid >> 7;
        float s = 0.f;
        for (int r = hf * 64; r < hf * 64 + 64; r++) {
            uint32_t off = (uint32_t)((col >> 6) * 16384) + SW128((uint32_t)(r * 128 + (col & 63) * 2));
            s += __bfloat162float(*(__nv_bfloat16*)(sb + CB_SAH + off))
               + __bfloat162float(*(__nv_bfloat16*)(sb + CB_SAL + off));
        }
        ((float*)(sb + CB_SSUM))[hf * 128 + col] = s;
    }
    __syncthreads();

    float* sN = (float*)(sb + CB_SNORM);
    float* sC = (float*)(sb + CB_SCOEF);
    if (tid < 128) {
        sC[tid] = 1.f / fmaxf(sN[tid * 4], EPSF);
        float* ss = (float*)(sb + CB_SSUM);
        nsum[(size_t)(h * 128 + blockIdx.x) * DD + tid] = ss[tid] + ss[128 + tid];
    }
    __syncthreads();

    float acc[2][8][4];
    #pragma unroll
    for (int t = 0; t < 2; t++)
        #pragma unroll
        for (int j = 0; j < 8; j++)
            #pragma unroll
            for (int p = 0; p < 4; p++) acc[t][j][p] = 0.f;
    bank_mma(sal, sal + CB_SB, wm, wn, lane, acc);

    // dv = v - acc*inv, written to smem bf16 hi/lo (reuse bank0 buffer at CB_SB)
    __syncthreads();   // all warps done reading bank0 from CB_SB
    #pragma unroll
    for (int t = 0; t < 2; t++) {
        int rloc = wm * 32 + t * 16 + (lane >> 2);
        float invA = sC[rloc], invB = sC[rloc + 8];
        int rr = row0 + rloc;
        #pragma unroll
        for (int j = 0; j < 8; j++) {
            int eloc = wn * 64 + j * 8 + (lane & 3) * 2;
            int col = h * DD + eloc;
            float2 v0 = *(const float2*)&v[(size_t)rr * HIDC + col];
            float2 v1 = *(const float2*)&v[(size_t)(rr + 8) * HIDC + col];
            float d00 = v0.x - acc[t][j][0] * invA, d01 = v0.y - acc[t][j][1] * invA;
            float d10 = v1.x - acc[t][j][2] * invB, d11 = v1.y - acc[t][j][3] * invB;
            uint32_t off0 = ((uint32_t)(eloc >> 6) << 14) + SW128((uint32_t)(rloc * 128 + (eloc & 63) * 2));
            uint32_t off1 = ((uint32_t)(eloc >> 6) << 14) + SW128((uint32_t)((rloc + 8) * 128 + (eloc & 63) * 2));
            __nv_bfloat16 h00 = __float2bfloat16(d00), h01 = __float2bfloat16(d01);
            __nv_bfloat16 h10 = __float2bfloat16(d10), h11 = __float2bfloat16(d11);
            *(__nv_bfloat162*)(sb + CB_SB + off0) = __nv_bfloat162(h00, h01);
            *(__nv_bfloat162*)(sb + CB_SB + off1) = __nv_bfloat162(h10, h11);
            *(__nv_bfloat162*)(sb + CB_SB + 32768 + off0) =
                __nv_bfloat162(__float2bfloat16(d00 - __bfloat162float(h00)),
                               __float2bfloat16(d01 - __bfloat162float(h01)));
            *(__nv_bfloat162*)(sb + CB_SB + 32768 + off1) =
                __nv_bfloat162(__float2bfloat16(d10 - __bfloat162float(h10)),
                               __float2bfloat16(d11 - __bfloat162float(h11)));
        }
    }
    __syncthreads();

    // P = sk^T @ dv  (both operands k(=r)-major in smem -> ldmatrix.trans)
    float pac[2][8][4];
    #pragma unroll
    for (int t = 0; t < 2; t++)
        #pragma unroll
        for (int j = 0; j < 8; j++)
            #pragma unroll
            for (int p = 0; p < 4; p++) pac[t][j][p] = 0.f;

    #pragma unroll
    for (int ks = 0; ks < 8; ks++) {
        int rA = ks * 16 + (lane & 7) + ((lane >> 4) & 1) * 8;
        uint32_t ah[2][4], al[2][4];
        #pragma unroll
        for (int t = 0; t < 2; t++) {
            int dseg = wm * 32 + t * 16 + ((lane >> 3) & 1) * 8;
            uint32_t addr = sal + CB_SAH + ((uint32_t)(dseg >> 6) << 14) +
                SW128((uint32_t)(rA * 128 + (dseg & 63) * 2));
            ldsm4t(ah[t], addr);
            ldsm4t(al[t], addr + 32768);
        }
        int rB = ks * 16 + (lane & 7) + ((lane >> 3) & 1) * 8;
        #pragma unroll
        for (int eg = 0; eg < 4; eg++) {
            int eseg = wn * 64 + eg * 16 + ((lane >> 4) & 1) * 8;
            uint32_t baddr = sal + CB_SB + ((uint32_t)(eseg >> 6) << 14) +
                SW128((uint32_t)(rB * 128 + (eseg & 63) * 2));
            uint32_t bh[4], bl[4];
            ldsm4t(bh, baddr);
            ldsm4t(bl, baddr + 32768);
            #pragma unroll
            for (int t = 0; t < 2; t++) {
                mma_bf16(pac[t][eg * 2 + 0], ah[t], bh);
                mma_bf16(pac[t][eg * 2 + 0], ah[t], bl);
                mma_bf16(pac[t][eg * 2 + 0], al[t], bh);
                mma_bf16(pac[t][eg * 2 + 1], ah[t], bh + 2);
                mma_bf16(pac[t][eg * 2 + 1], ah[t], bl + 2);
                mma_bf16(pac[t][eg * 2 + 1], al[t], bh + 2);
            }
        }
    }

    size_t base = ((size_t)(h * 128 + blockIdx.x)) << 14;   // 128x128 floats per slice
    #pragma unroll
    for (int t = 0; t < 2; t++) {
        int d0 = wm * 32 + t * 16 + (lane >> 2);
        #pragma unroll
        for (int j = 0; j < 8; j++) {
            int col = wn * 64 + j * 8 + (lane & 3) * 2;
            *(float2*)&part[base + (size_t)d0 * 128 + col]       = make_float2(pac[t][j][0], pac[t][j][1]);
            *(float2*)&part[base + (size_t)(d0 + 8) * 128 + col] = make_float2(pac[t][j][2], pac[t][j][3]);
        }
    }
}

// ===================== reductions =====================
__global__ void reduce_mem_kernel(const float* __restrict__ part,
                                  const float* __restrict__ memories,
                                  float* __restrict__ out)
{
    int t = blockIdx.x * blockDim.x + threadIdx.x;
    int h = t >> 14;
    int rem = t & 16383;
    float s = 0.f;
    #pragma unroll 8
    for (int sl = 0; sl < 128; sl++)
        s += part[((size_t)(h * 128 + sl) << 14) + rem];
    out[OUT_MEM + t] = memories[(size_t)h * DD * DD + rem] + s * (1.f / (float)BQ);
}

__global__ void reduce_norm_kernel(const float* __restrict__ nsum,
                                   const float* __restrict__ mnorms,
                                   float* __restrict__ out)
{
    int t = blockIdx.x * blockDim.x + threadIdx.x;
    int h = t >> 7, d = t & 127;
    float s = 0.f;
    for (int b = 0; b < 128; b++)
        s += nsum[(size_t)(h * 128 + b) * DD + d];
    out[OUT_NORM + t] = mnorms[(size_t)h * DD + d] + s * 0.25f;
}

// ---------------------------------------------------------------------------
extern "C" void kernel_launch(void* const* d_in, const int* in_sizes, int n_in,
                              void* d_out, int out_size)
{
    const float* hs = (const float*)d_in[0];
    const float* Wq = (const float*)d_in[1];
    const float* Wk = (const float*)d_in[2];
    const float* Wv = (const float*)d_in[3];
    const float* Wo = (const float*)d_in[4];
    const float* bw = (const float*)d_in[5];
    const float* mem = (const float*)d_in[6];
    const float* mnm = (const float*)d_in[7];
    float* out = (float*)d_out;

    float *pq, *pk, *pv, *ppart, *pnsum;
    __nv_bfloat16 *hsh, *hsl, *wh, *wl, *cbh, *cbl, *mTh, *mTl, *nTh, *nTl;
    cudaGetSymbolAddress((void**)&pq, g_q);
    cudaGetSymbolAddress((void**)&pk, g_k);
    cudaGetSymbolAddress((void**)&pv, g_v);
    cudaGetSymbolAddress((void**)&ppart, g_part);
    cudaGetSymbolAddress((void**)&pnsum, g_nsum);
    cudaGetSymbolAddress((void**)&hsh, g_hs_hi);
    cudaGetSymbolAddress((void**)&hsl, g_hs_lo);
    cudaGetSymbolAddress((void**)&wh, g_w_hi);
    cudaGetSymbolAddress((void**)&wl, g_w_lo);
    cudaGetSymbolAddress((void**)&cbh, g_cb_hi);
    cudaGetSymbolAddress((void**)&cbl, g_cb_lo);
    cudaGetSymbolAddress((void**)&mTh, g_mTh);
    cudaGetSymbolAddress((void**)&mTl, g_mTl);
    cudaGetSymbolAddress((void**)&nTh, g_nTh);
    cudaGetSymbolAddress((void**)&nTl, g_nTl);

    static int smem_set = 0;
    if (!smem_set) {
        cudaFuncSetAttribute(hgemm_kernel, cudaFuncAttributeMaxDynamicSharedMemorySize, HG_SMEM);
        cudaFuncSetAttribute(combined_hmma, cudaFuncAttributeMaxDynamicSharedMemorySize, CB_SMEM);
        cudaFuncSetAttribute(deltav_hmma, cudaFuncAttributeMaxDynamicSharedMemorySize, CB_SMEM);
        smem_set = 1;
    }

    const size_t WSZ = (size_t)HIDC * HIDC;
    dim3 gg(HIDC / 256, BQ / 128);   // (8, 128)

    prep_kernel<<<1, 128>>>(bw, mnm);                                         // 0
    cvt_split_kernel<<<(BQ * (size_t)HIDC) / 4 / 256, 256>>>(hs, hsh, hsl);   // 1
    cvt_split_kernel<<<WSZ / 4 / 256, 256>>>(Wq, wh + 0 * WSZ, wl + 0 * WSZ); // 2
    cvt_split_kernel<<<WSZ / 4 / 256, 256>>>(Wk, wh + 1 * WSZ, wl + 1 * WSZ); // 3
    cvt_split_kernel<<<WSZ / 4 / 256, 256>>>(Wv, wh + 2 * WSZ, wl + 2 * WSZ); // 4
    hgemm_kernel<<<gg, 256, HG_SMEM>>>(hsh, hsl, wh + 0 * WSZ, wl + 0 * WSZ, pq, HIDC); // 5
    hgemm_kernel<<<gg, 256, HG_SMEM>>>(hsh, hsl, wh + 1 * WSZ, wl + 1 * WSZ, pk, HIDC); // 6
    cvt_split_kernel<<<WSZ / 4 / 256, 256>>>(Wo, wh + 3 * WSZ, wl + 3 * WSZ); // 7
    hgemm_kernel<<<gg, 256, HG_SMEM>>>(hsh, hsl, wh + 2 * WSZ, wl + 2 * WSZ, pv, HIDC); // 8

    prep2_kernel<<<NBANK * NH, 256>>>(mem, mTh, mTl);
    normt_kernel<<<NH, 256>>>(mnm, nTh, nTl);

    combined_hmma<<<dim3(BQ / 128, NH), 256, CB_SMEM>>>(pq, mTh, mTl, nTh, nTl, cbh, cbl);
    deltav_hmma<<<dim3(BQ / 128, NH), 256, CB_SMEM>>>(pk, pv, mTh, mTl, nTh, nTl, pnsum, ppart);

    reduce_mem_kernel<<<(NH * DD * DD) / 256, 256>>>(ppart, mem, out);
    reduce_norm_kernel<<<(NH * DD) / 256, 256>>>(pnsum, mnm, out);

    hgemm_kernel<<<gg, 256, HG_SMEM>>>(cbh, cbl, wh + 3 * WSZ, wl + 3 * WSZ, out, HIDC);
}